// round 2
// baseline (speedup 1.0000x reference)
#include <cuda_runtime.h>
#include <math.h>

// ---------------- scratch (device globals; no allocation APIs) ----------------
__device__ float g_A[(size_t)4096 * 8192];   // cconv A tensor [n][64cells][128c]
__device__ float g_conv[4096 * 128];
__device__ float g_featx[4096 * 128];
__device__ float g_featy[4096 * 128];
__device__ float g_h[4096 * 128];
__device__ float g_q[4096 * 128];            // head-major [h][n][32]
__device__ float g_k[4096 * 128];
__device__ float g_v[4096 * 128];
__device__ float g_attn[4096 * 128];
__device__ float g_op[4096 * 128];
__device__ float g_h1[4096 * 128];
__device__ float g_ffh[4096 * 512];
__device__ float g_stats[512];               // [0..127] bn mean, [128..255] bn inv, [256] pos mean, [257] pos inv-std

__device__ __forceinline__ float* resolve(int id) {
    switch (id) {
        case 0:  return g_A;
        case 1:  return g_conv;
        case 2:  return g_featx;
        case 3:  return g_featy;
        case 4:  return g_h;
        case 5:  return g_q;
        case 6:  return g_k;
        case 7:  return g_v;
        case 8:  return g_attn;
        case 9:  return g_op;
        case 10: return g_h1;
        case 11: return g_ffh;
        default: return g_stats;
    }
}

// fast exp on FMA pipe: e^x = 2^(x*log2e); degree-6 poly of 2^f on f in [0,1).
__device__ __forceinline__ float fast_exp(float x) {
    float t = x * 1.4426950408889634f;
    t = fmaxf(t, -126.0f);
    float fi = floorf(t);
    float f  = t - fi;
    float r  = 1.5403530393381606e-4f;
    r = fmaf(r, f, 1.3333558146428443e-3f);
    r = fmaf(r, f, 9.6181291076284770e-3f);
    r = fmaf(r, f, 5.5504108664821580e-2f);
    r = fmaf(r, f, 2.4022650695910070e-1f);
    r = fmaf(r, f, 6.9314718055994530e-1f);
    r = fmaf(r, f, 1.0f);
    return r * __int_as_float(((int)fi + 127) << 23);
}

// ---------------- utility: zero a scratch buffer ----------------
__global__ void k_zero(int id, int n) {
    float* p = resolve(id);
    int i = blockIdx.x * blockDim.x + threadIdx.x;
    if (i < n) p[i] = 0.f;
}

// ---------------- pos stats: mean/std(ddof=1) of pos[:,0] ----------------
__global__ void k_posstats(const float* __restrict__ pos) {
    __shared__ float ss[256], sq[256];
    int t = threadIdx.x;
    float s = 0.f, q = 0.f;
    for (int i = t; i < 4096; i += 256) {
        float v = pos[i * 3];
        s += v; q = fmaf(v, v, q);
    }
    ss[t] = s; sq[t] = q;
    __syncthreads();
    for (int o = 128; o > 0; o >>= 1) {
        if (t < o) { ss[t] += ss[t + o]; sq[t] += sq[t + o]; }
        __syncthreads();
    }
    if (t == 0) {
        float m  = ss[0] / 4096.f;
        float sd = sqrtf(fmaxf((sq[0] - 4096.f * m * m) / 4095.f, 0.f));
        g_stats[256] = m;
        g_stats[257] = 1.f / (sd + 1e-8f);
    }
}

// ---------------- cconv stage A: scatter-aggregate into A[n][64][128] ----------------
__global__ __launch_bounds__(128) void k_stageA(const float* __restrict__ feat,
                                                const float* __restrict__ pos,
                                                const int* __restrict__ nbr) {
    __shared__ float A[64 * 128];
    __shared__ float wgt[80][8];
    __shared__ int   cel[80][8];
    __shared__ int   jl[80];
    __shared__ int   vld[80];
    int i = blockIdx.x;
    int t = threadIdx.x;
    for (int u = t; u < 64 * 128; u += 128) A[u] = 0.f;
    if (t < 80) {
        int j = nbr[i * 80 + t];
        jl[t] = j;
        const float R = 0.1125f;   // float32(RADIUS)
        float rx = (pos[3 * j + 0] - pos[3 * i + 0]) / R;
        float ry = (pos[3 * j + 1] - pos[3 * i + 1]) / R;
        float rz = (pos[3 * j + 2] - pos[3 * i + 2]) / R;
        float r2 = rx * rx + ry * ry + rz * rz;
        float win = 0.f;
        if (j != i) {
            float w1 = 1.f - r2;
            win = fminf(fmaxf(w1 * w1 * w1, 0.f), 1.f);
        }
        vld[t] = (win > 0.f) ? 1 : 0;
        float nrm  = sqrtf(fmaxf(r2, 1e-12f));
        float linf = fmaxf(fmaxf(fabsf(rx), fabsf(ry)), fabsf(rz));
        linf = fmaxf(linf, 1e-9f);
        float sc = nrm / linf;
        float gx = fminf(fmaxf(fmaf(rx * sc, 1.5f, 1.5f), 0.f), 3.f);
        float gy = fminf(fmaxf(fmaf(ry * sc, 1.5f, 1.5f), 0.f), 3.f);
        float gz = fminf(fmaxf(fmaf(rz * sc, 1.5f, 1.5f), 0.f), 3.f);
        float fx = fminf(floorf(gx), 2.f);
        float fy = fminf(floorf(gy), 2.f);
        float fz = fminf(floorf(gz), 2.f);
        float tx = gx - fx, ty = gy - fy, tz = gz - fz;
        int base = (int)fx * 16 + (int)fy * 4 + (int)fz;
        #pragma unroll
        for (int dx = 0; dx < 2; dx++)
            #pragma unroll
            for (int dy = 0; dy < 2; dy++)
                #pragma unroll
                for (int dz = 0; dz < 2; dz++) {
                    float cw = (dx ? tx : 1.f - tx) * (dy ? ty : 1.f - ty) * (dz ? tz : 1.f - tz);
                    int q = dx * 4 + dy * 2 + dz;
                    wgt[t][q] = win * cw;
                    cel[t][q] = base + dx * 16 + dy * 4 + dz;
                }
    }
    __syncthreads();
    int c = t;
    for (int nb = 0; nb < 80; nb++) {
        if (!vld[nb]) continue;            // CTA-uniform skip
        float f = feat[(size_t)jl[nb] * 128 + c];
        #pragma unroll
        for (int q = 0; q < 8; q++)
            A[cel[nb][q] * 128 + c] += wgt[nb][q] * f;
    }
    __syncthreads();
    float* dst = g_A + (size_t)i * 8192;
    for (int u = t; u < 8192; u += 128) dst[u] = A[u];
}

// ---------------- GEMM: Out[M][O] over In[M][Kdim] ----------------
// WT=true:  W is [O][Kdim] (out = In @ W.T).  WT=false: W is [Kdim][O].
// flags: 1=relu, 2=head-layout store, 4=split-K atomic accumulate
template <bool WT>
__global__ __launch_bounds__(128) void k_gemm(int inId, const float* __restrict__ W,
                                              const float* __restrict__ bias, int outId,
                                              int Kdim, int O, int flags, int kchunk) {
    __shared__ __align__(16) float InsT[16][64];
    __shared__ __align__(16) float Ws[16][128];
    const float* In = resolve(inId);
    float* Out = resolve(outId);
    int t = threadIdx.x;
    int bm0 = blockIdx.x * 64;
    int bn0 = blockIdx.y * 128;
    int kstart = blockIdx.z * kchunk;
    int kend = kstart + kchunk;
    int tr = t >> 4, tc = t & 15;
    float acc[8][8];
    #pragma unroll
    for (int a = 0; a < 8; a++)
        #pragma unroll
        for (int b = 0; b < 8; b++) acc[a][b] = 0.f;

    for (int kb = kstart; kb < kend; kb += 16) {
        __syncthreads();
        #pragma unroll
        for (int e = 0; e < 2; e++) {
            int f = t * 2 + e;
            int row = f >> 2;
            int k4 = (f & 3) * 4;
            float4 v = *(const float4*)&In[(size_t)(bm0 + row) * Kdim + kb + k4];
            InsT[k4 + 0][row] = v.x; InsT[k4 + 1][row] = v.y;
            InsT[k4 + 2][row] = v.z; InsT[k4 + 3][row] = v.w;
        }
        if (WT) {
            #pragma unroll
            for (int e = 0; e < 4; e++) {
                float4 v = *(const float4*)&W[(size_t)(bn0 + t) * Kdim + kb + e * 4];
                Ws[e * 4 + 0][t] = v.x; Ws[e * 4 + 1][t] = v.y;
                Ws[e * 4 + 2][t] = v.z; Ws[e * 4 + 3][t] = v.w;
            }
        } else {
            #pragma unroll
            for (int e = 0; e < 4; e++) {
                int f = t * 4 + e;
                int k = f >> 5;
                int o4 = (f & 31) * 4;
                *(float4*)&Ws[k][o4] = *(const float4*)&W[(size_t)(kb + k) * O + bn0 + o4];
            }
        }
        __syncthreads();
        #pragma unroll
        for (int k = 0; k < 16; k++) {
            float a[8], w[8];
            *(float4*)&a[0] = *(const float4*)&InsT[k][tr * 8];
            *(float4*)&a[4] = *(const float4*)&InsT[k][tr * 8 + 4];
            *(float4*)&w[0] = *(const float4*)&Ws[k][tc * 8];
            *(float4*)&w[4] = *(const float4*)&Ws[k][tc * 8 + 4];
            #pragma unroll
            for (int ii = 0; ii < 8; ii++)
                #pragma unroll
                for (int jj = 0; jj < 8; jj++)
                    acc[ii][jj] = fmaf(a[ii], w[jj], acc[ii][jj]);
        }
    }
    #pragma unroll
    for (int ii = 0; ii < 8; ii++) {
        int n = bm0 + tr * 8 + ii;
        #pragma unroll
        for (int jj = 0; jj < 8; jj++) {
            int o = bn0 + tc * 8 + jj;
            float v = acc[ii][jj];
            if (flags & 4) {
                if (blockIdx.z == 0) v += bias[o];
                atomicAdd(&Out[(size_t)n * O + o], v);
            } else {
                v += bias[o];
                if (flags & 1) v = fmaxf(v, 0.f);
                if (flags & 2) Out[((size_t)(o >> 5) * 4096 + n) * 32 + (o & 31)] = v;
                else           Out[(size_t)n * O + o] = v;
            }
        }
    }
}

// ---------------- batch-norm stats (per channel over N) ----------------
__global__ void k_bnstats() {
    __shared__ float ss[128], sq[128];
    int c = blockIdx.x, t = threadIdx.x;
    float s = 0.f, q = 0.f;
    for (int r = t; r < 4096; r += 128) {
        float v = g_conv[(size_t)r * 128 + c];
        s += v; q = fmaf(v, v, q);
    }
    ss[t] = s; sq[t] = q;
    __syncthreads();
    for (int o = 64; o > 0; o >>= 1) {
        if (t < o) { ss[t] += ss[t + o]; sq[t] += sq[t + o]; }
        __syncthreads();
    }
    if (t == 0) {
        float m = ss[0] / 4096.f;
        float var = sq[0] / 4096.f - m * m;
        g_stats[c] = m;
        g_stats[128 + c] = rsqrtf(var + 1e-5f);
    }
}

__global__ void k_bnrelu(int inId, int outId, const float* __restrict__ g,
                         const float* __restrict__ b) {
    int n = blockIdx.x, c = threadIdx.x;
    const float* In = resolve(inId);
    float* O = resolve(outId);
    float v = (In[(size_t)n * 128 + c] - g_stats[c]) * g_stats[128 + c] * g[c] + b[c];
    O[(size_t)n * 128 + c] = fmaxf(v, 0.f);
}

// ---------------- h = feat + pos_encoding ----------------
__global__ void k_addpe(int featId, const float* __restrict__ pos) {
    int n = blockIdx.x, t = threadIdx.x;
    float px = (pos[n * 3] - g_stats[256]) * g_stats[257];
    int i = t >> 1;
    float ang = px * expf(-0.14391156831212798f * (float)i);
    float pe = (t & 1) ? cosf(ang) : sinf(ang);
    g_h[(size_t)n * 128 + t] = resolve(featId)[(size_t)n * 128 + t] + pe;
}

// ---------------- flash attention: thread-per-query ----------------
__global__ __launch_bounds__(128) void k_attn() {
    __shared__ float Ks[1024], Vs[1024];
    int head = blockIdx.y;
    int t = threadIdx.x;
    int qi = blockIdx.x * 128 + t;
    const float4* qp = (const float4*)(g_q + ((size_t)head * 4096 + qi) * 32);
    const float sc = 0.17677669529663687f;   // 1/sqrt(32)
    float Q[32], acc[32];
    #pragma unroll
    for (int d4 = 0; d4 < 8; d4++) {
        float4 v = qp[d4];
        Q[4 * d4 + 0] = v.x * sc; Q[4 * d4 + 1] = v.y * sc;
        Q[4 * d4 + 2] = v.z * sc; Q[4 * d4 + 3] = v.w * sc;
    }
    #pragma unroll
    for (int d = 0; d < 32; d++) acc[d] = 0.f;
    float m = -1e30f, l = 0.f;
    for (int kt = 0; kt < 128; kt++) {
        __syncthreads();
        const float4* kp = (const float4*)(g_k + ((size_t)head * 4096 + kt * 32) * 32);
        const float4* vp = (const float4*)(g_v + ((size_t)head * 4096 + kt * 32) * 32);
        ((float4*)Ks)[t] = kp[t]; ((float4*)Ks)[t + 128] = kp[t + 128];
        ((float4*)Vs)[t] = vp[t]; ((float4*)Vs)[t + 128] = vp[t + 128];
        __syncthreads();
        float sv[32];
        #pragma unroll
        for (int k = 0; k < 32; k++) {
            const float4* kr = (const float4*)(Ks + k * 32);
            float s0 = 0.f, s1 = 0.f, s2 = 0.f, s3 = 0.f;
            #pragma unroll
            for (int d4 = 0; d4 < 8; d4++) {
                float4 kk = kr[d4];
                s0 = fmaf(Q[4 * d4 + 0], kk.x, s0);
                s1 = fmaf(Q[4 * d4 + 1], kk.y, s1);
                s2 = fmaf(Q[4 * d4 + 2], kk.z, s2);
                s3 = fmaf(Q[4 * d4 + 3], kk.w, s3);
            }
            sv[k] = (s0 + s1) + (s2 + s3);
        }
        float tm = sv[0];
        #pragma unroll
        for (int k = 1; k < 32; k++) tm = fmaxf(tm, sv[k]);
        float mn = fmaxf(m, tm);
        float corr = fast_exp(m - mn);
        m = mn; l *= corr;
        #pragma unroll
        for (int d = 0; d < 32; d++) acc[d] *= corr;
        #pragma unroll
        for (int k = 0; k < 32; k++) {
            float p = fast_exp(sv[k] - m);
            l += p;
            const float4* vr = (const float4*)(Vs + k * 32);
            #pragma unroll
            for (int d4 = 0; d4 < 8; d4++) {
                float4 vv = vr[d4];
                acc[4 * d4 + 0] = fmaf(p, vv.x, acc[4 * d4 + 0]);
                acc[4 * d4 + 1] = fmaf(p, vv.y, acc[4 * d4 + 1]);
                acc[4 * d4 + 2] = fmaf(p, vv.z, acc[4 * d4 + 2]);
                acc[4 * d4 + 3] = fmaf(p, vv.w, acc[4 * d4 + 3]);
            }
        }
    }
    float inv = 1.f / l;
    float4* op = (float4*)(g_attn + (size_t)qi * 128 + head * 32);
    #pragma unroll
    for (int d4 = 0; d4 < 8; d4++) {
        float4 o;
        o.x = acc[4 * d4 + 0] * inv; o.y = acc[4 * d4 + 1] * inv;
        o.z = acc[4 * d4 + 2] * inv; o.w = acc[4 * d4 + 3] * inv;
        op[d4] = o;
    }
}

// ---------------- layernorm of (A + B) ----------------
__global__ void k_ln(int aId, int bId, int outId, const float* __restrict__ g,
                     const float* __restrict__ b) {
    __shared__ float rs[4], rq[4];
    int n = blockIdx.x, t = threadIdx.x;
    const float* A = resolve(aId);
    const float* B = resolve(bId);
    float* O = resolve(outId);
    float v = A[(size_t)n * 128 + t] + B[(size_t)n * 128 + t];
    float s = v, q = v * v;
    #pragma unroll
    for (int o = 16; o > 0; o >>= 1) {
        s += __shfl_xor_sync(0xffffffffu, s, o);
        q += __shfl_xor_sync(0xffffffffu, q, o);
    }
    int w = t >> 5;
    if ((t & 31) == 0) { rs[w] = s; rq[w] = q; }
    __syncthreads();
    s = rs[0] + rs[1] + rs[2] + rs[3];
    q = rq[0] + rq[1] + rq[2] + rq[3];
    float mean = s * (1.f / 128.f);
    float var = q * (1.f / 128.f) - mean * mean;
    O[(size_t)n * 128 + t] = (v - mean) * rsqrtf(var + 1e-5f) * g[t] + b[t];
}

// ---------------- final gating ----------------
__global__ void k_final(const float* __restrict__ x, const float* __restrict__ y,
                        float* __restrict__ out) {
    int i = blockIdx.x * 256 + threadIdx.x;
    float z = g_featx[i] + g_featy[i];
    float w = 1.f / (1.f + fast_exp(-z));
    out[i] = 2.f * (x[i] * w + y[i] * (1.f - w));
}

// ---------------- host orchestration ----------------
static void run_block(int featId, const float* pos,
                      const float* Wq, const float* bq, const float* Wk, const float* bk,
                      const float* Wv, const float* bv, const float* Wo, const float* bo,
                      const float* l1g, const float* l1b, const float* W1, const float* b1,
                      const float* W2, const float* b2, const float* l2g, const float* l2b) {
    k_addpe<<<4096, 128>>>(featId, pos);
    k_gemm<true><<<dim3(64, 1, 1), 128>>>(4, Wq, bq, 5, 128, 128, 2, 128);
    k_gemm<true><<<dim3(64, 1, 1), 128>>>(4, Wk, bk, 6, 128, 128, 2, 128);
    k_gemm<true><<<dim3(64, 1, 1), 128>>>(4, Wv, bv, 7, 128, 128, 2, 128);
    k_attn<<<dim3(32, 4), 128>>>();
    k_gemm<true><<<dim3(64, 1, 1), 128>>>(8, Wo, bo, 9, 128, 128, 0, 128);
    k_ln<<<4096, 128>>>(featId, 9, 10, l1g, l1b);
    k_gemm<true><<<dim3(64, 4, 1), 128>>>(10, W1, b1, 11, 128, 512, 1, 128);
    k_gemm<true><<<dim3(64, 1, 1), 128>>>(11, W2, b2, 4, 512, 128, 0, 512);
    k_ln<<<4096, 128>>>(10, 4, featId, l2g, l2b);
}

extern "C" void kernel_launch(void* const* d_in, const int* in_sizes, int n_in,
                              void* d_out, int out_size) {
    const float* x   = (const float*)d_in[0];
    const float* y   = (const float*)d_in[1];
    const float* pos = (const float*)d_in[2];
    const int*   nbr = (const int*)d_in[3];
    // d_in[4] = nbr_mask, redundant (mask == (idx != i)); ignored.
    const float* Wx  = (const float*)d_in[5];
    const float* bx  = (const float*)d_in[6];
    const float* bxg = (const float*)d_in[7];
    const float* bxb = (const float*)d_in[8];
    const float* Wy  = (const float*)d_in[9];
    const float* by  = (const float*)d_in[10];
    const float* byg = (const float*)d_in[11];
    const float* byb = (const float*)d_in[12];
    const float* Wq  = (const float*)d_in[13];
    const float* bq  = (const float*)d_in[14];
    const float* Wk  = (const float*)d_in[15];
    const float* bk  = (const float*)d_in[16];
    const float* Wv  = (const float*)d_in[17];
    const float* bv  = (const float*)d_in[18];
    const float* Wo  = (const float*)d_in[19];
    const float* bo  = (const float*)d_in[20];
    const float* l1g = (const float*)d_in[21];
    const float* l1b = (const float*)d_in[22];
    const float* W1  = (const float*)d_in[23];
    const float* b1  = (const float*)d_in[24];
    const float* W2  = (const float*)d_in[25];
    const float* b2  = (const float*)d_in[26];
    const float* l2g = (const float*)d_in[27];
    const float* l2b = (const float*)d_in[28];
    float* out = (float*)d_out;

    k_posstats<<<1, 256>>>(pos);

    // cconv(x) -> bn -> relu -> g_featx
    k_stageA<<<4096, 128>>>(x, pos, nbr);
    k_zero<<<2048, 256>>>(1, 4096 * 128);
    k_gemm<false><<<dim3(64, 1, 4), 128>>>(0, Wx, bx, 1, 8192, 128, 4, 2048);
    k_bnstats<<<128, 128>>>();
    k_bnrelu<<<4096, 128>>>(1, 2, bxg, bxb);

    // cconv(y) -> bn -> relu -> g_featy
    k_stageA<<<4096, 128>>>(y, pos, nbr);
    k_zero<<<2048, 256>>>(1, 4096 * 128);
    k_gemm<false><<<dim3(64, 1, 4), 128>>>(0, Wy, by, 1, 8192, 128, 4, 2048);
    k_bnstats<<<128, 128>>>();
    k_bnrelu<<<4096, 128>>>(1, 3, byg, byb);

    // transformer block on each feature (same weights)
    run_block(2, pos, Wq, bq, Wk, bk, Wv, bv, Wo, bo, l1g, l1b, W1, b1, W2, b2, l2g, l2b);
    run_block(3, pos, Wq, bq, Wk, bk, Wv, bv, Wo, bo, l1g, l1b, W1, b1, W2, b2, l2g, l2b);

    // final sigmoid gate
    k_final<<<2048, 256>>>(x, y, out);
}

// round 11
// speedup vs baseline: 1.8968x; 1.8968x over previous
#include <cuda_runtime.h>
#include <cuda_bf16.h>
#include <math.h>
#include <stdint.h>

// ================= scratch (device globals; no allocation APIs) =================
#define NPTS 4096
__device__ __nv_bfloat16 g_Ah[2ull * NPTS * 8192];
__device__ __nv_bfloat16 g_Al[2ull * NPTS * 8192];
__device__ __nv_bfloat16 g_Wh[2ull * 128 * 8192];
__device__ __nv_bfloat16 g_Wl[2ull * 128 * 8192];
__device__ float g_conv[2][NPTS * 128];
__device__ float g_feat[2][NPTS * 128];
__device__ float g_h[2][NPTS * 128];
__device__ float g_q[2][NPTS * 128];      // head-major [h][n][32]
__device__ float g_k[2][NPTS * 128];
__device__ float g_v[2][NPTS * 128];
__device__ float g_attn[2][NPTS * 128];
__device__ float g_op[2][NPTS * 128];
__device__ float g_h1[2][NPTS * 128];
__device__ float g_ffh[2][NPTS * 512];
__device__ float g_stats[2][256];         // per-feat bn mean[0:128], inv-std[128:256]
__device__ float g_pstats[2];             // pos mean, pos inv-std

__device__ __forceinline__ float* resolve(int id, int feat) {
    switch (id) {
        case 1:  return g_conv[feat];
        case 2:  return g_feat[feat];
        case 4:  return g_h[feat];
        case 5:  return g_q[feat];
        case 6:  return g_k[feat];
        case 7:  return g_v[feat];
        case 8:  return g_attn[feat];
        case 9:  return g_op[feat];
        case 10: return g_h1[feat];
        default: return g_ffh[feat];
    }
}

// ================= baseline-PTX helpers (sm_103-safe; NO tcgen05) =================
static __device__ __forceinline__ uint32_t smem_u32(const void* p) {
    uint32_t a;
    asm("{ .reg .u64 t; cvta.to.shared.u64 t, %1; cvt.u32.u64 %0, t; }" : "=r"(a) : "l"(p));
    return a;
}
static __device__ __forceinline__ void cp_async16(uint32_t dst, const void* src) {
    asm volatile("cp.async.cg.shared.global [%0], [%1], 16;" :: "r"(dst), "l"(src) : "memory");
}
#define CP_COMMIT() asm volatile("cp.async.commit_group;" ::: "memory")
#define CP_WAIT(n)  asm volatile("cp.async.wait_group %0;" :: "n"(n) : "memory")

static __device__ __forceinline__ void ldm_x4(uint32_t* r, uint32_t addr) {
    asm volatile("ldmatrix.sync.aligned.m8n8.x4.shared.b16 {%0,%1,%2,%3}, [%4];"
                 : "=r"(r[0]), "=r"(r[1]), "=r"(r[2]), "=r"(r[3]) : "r"(addr));
}
static __device__ __forceinline__ void mma16816(float* c, const uint32_t* a, const uint32_t* b) {
    asm volatile("mma.sync.aligned.m16n8k16.row.col.f32.bf16.bf16.f32 "
                 "{%0,%1,%2,%3}, {%4,%5,%6,%7}, {%8,%9}, {%0,%1,%2,%3};"
                 : "+f"(c[0]), "+f"(c[1]), "+f"(c[2]), "+f"(c[3])
                 : "r"(a[0]), "r"(a[1]), "r"(a[2]), "r"(a[3]), "r"(b[0]), "r"(b[1]));
}

// fast exp on FMA pipe
__device__ __forceinline__ float fast_exp(float x) {
    float t = x * 1.4426950408889634f;
    t = fmaxf(t, -126.0f);
    float fi = floorf(t);
    float f  = t - fi;
    float r  = 1.5403530393381606e-4f;
    r = fmaf(r, f, 1.3333558146428443e-3f);
    r = fmaf(r, f, 9.6181291076284770e-3f);
    r = fmaf(r, f, 5.5504108664821580e-2f);
    r = fmaf(r, f, 2.4022650695910070e-1f);
    r = fmaf(r, f, 6.9314718055994530e-1f);
    r = fmaf(r, f, 1.0f);
    return r * __int_as_float(((int)fi + 127) << 23);
}

// ================= pos stats =================
__global__ void k_posstats(const float* __restrict__ pos) {
    __shared__ float ss[256], sq[256];
    int t = threadIdx.x;
    float s = 0.f, q = 0.f;
    for (int i = t; i < NPTS; i += 256) {
        float v = pos[i * 3];
        s += v; q = fmaf(v, v, q);
    }
    ss[t] = s; sq[t] = q;
    __syncthreads();
    for (int o = 128; o > 0; o >>= 1) {
        if (t < o) { ss[t] += ss[t + o]; sq[t] += sq[t + o]; }
        __syncthreads();
    }
    if (t == 0) {
        float m  = ss[0] / 4096.f;
        float sd = sqrtf(fmaxf((sq[0] - 4096.f * m * m) / 4095.f, 0.f));
        g_pstats[0] = m;
        g_pstats[1] = 1.f / (sd + 1e-8f);
    }
}

// ================= weight prep: transpose + bf16 hi/lo split -> W[o][k] =================
__global__ void k_prepW(const float* __restrict__ Wx, const float* __restrict__ Wy) {
    int feat = blockIdx.y;
    const float* W = feat ? Wy : Wx;
    __nv_bfloat16* Wh = g_Wh + (size_t)feat * 128 * 8192;
    __nv_bfloat16* Wl = g_Wl + (size_t)feat * 128 * 8192;
    int o = threadIdx.x;
    int k8 = blockIdx.x * 8;
    #pragma unroll
    for (int j = 0; j < 8; j++) {
        float v = W[(size_t)(k8 + j) * 128 + o];
        __nv_bfloat16 h = __float2bfloat16(v);
        __nv_bfloat16 l = __float2bfloat16(v - __bfloat162float(h));
        Wh[(size_t)o * 8192 + k8 + j] = h;
        Wl[(size_t)o * 8192 + k8 + j] = l;
    }
}

// ================= cconv stage A: scatter into A[n][64cells][128c], bf16 hi/lo out =================
__global__ __launch_bounds__(128) void k_stageA(const float* __restrict__ x,
                                                const float* __restrict__ y,
                                                const float* __restrict__ pos,
                                                const int* __restrict__ nbr) {
    __shared__ float A[64 * 128];
    __shared__ float wgt[80][8];
    __shared__ int   cel[80][8];
    __shared__ int   jl[80];
    __shared__ int   vld[80];
    int i = blockIdx.x;
    int feat = blockIdx.y;
    const float* src = feat ? y : x;
    int t = threadIdx.x;
    for (int u = t; u < 64 * 128; u += 128) A[u] = 0.f;
    if (t < 80) {
        int j = nbr[i * 80 + t];
        jl[t] = j;
        const float R = 0.1125f;
        float rx = (pos[3 * j + 0] - pos[3 * i + 0]) / R;
        float ry = (pos[3 * j + 1] - pos[3 * i + 1]) / R;
        float rz = (pos[3 * j + 2] - pos[3 * i + 2]) / R;
        float r2 = rx * rx + ry * ry + rz * rz;
        float win = 0.f;
        if (j != i) {
            float w1 = 1.f - r2;
            win = fminf(fmaxf(w1 * w1 * w1, 0.f), 1.f);
        }
        vld[t] = (win > 0.f) ? 1 : 0;
        float nrm  = sqrtf(fmaxf(r2, 1e-12f));
        float linf = fmaxf(fmaxf(fabsf(rx), fabsf(ry)), fabsf(rz));
        linf = fmaxf(linf, 1e-9f);
        float sc = nrm / linf;
        float gx = fminf(fmaxf(fmaf(rx * sc, 1.5f, 1.5f), 0.f), 3.f);
        float gy = fminf(fmaxf(fmaf(ry * sc, 1.5f, 1.5f), 0.f), 3.f);
        float gz = fminf(fmaxf(fmaf(rz * sc, 1.5f, 1.5f), 0.f), 3.f);
        float fx = fminf(floorf(gx), 2.f);
        float fy = fminf(floorf(gy), 2.f);
        float fz = fminf(floorf(gz), 2.f);
        float tx = gx - fx, ty = gy - fy, tz = gz - fz;
        int base = (int)fx * 16 + (int)fy * 4 + (int)fz;
        #pragma unroll
        for (int dx = 0; dx < 2; dx++)
            #pragma unroll
            for (int dy = 0; dy < 2; dy++)
                #pragma unroll
                for (int dz = 0; dz < 2; dz++) {
                    float cw = (dx ? tx : 1.f - tx) * (dy ? ty : 1.f - ty) * (dz ? tz : 1.f - tz);
                    int q = dx * 4 + dy * 2 + dz;
                    wgt[t][q] = win * cw;
                    cel[t][q] = base + dx * 16 + dy * 4 + dz;
                }
    }
    __syncthreads();
    int c = t;
    for (int nb = 0; nb < 80; nb++) {
        if (!vld[nb]) continue;
        float f = src[(size_t)jl[nb] * 128 + c];
        #pragma unroll
        for (int q = 0; q < 8; q++)
            A[cel[nb][q] * 128 + c] += wgt[nb][q] * f;
    }
    __syncthreads();
    __nv_bfloat16* dh = g_Ah + (size_t)feat * NPTS * 8192 + (size_t)i * 8192;
    __nv_bfloat16* dl = g_Al + (size_t)feat * NPTS * 8192 + (size_t)i * 8192;
    for (int u = t; u < 8192; u += 128) {
        float v = A[u];
        __nv_bfloat16 h = __float2bfloat16(v);
        dh[u] = h;
        dl[u] = __float2bfloat16(v - __bfloat162float(h));
    }
}

// ================= conv GEMM via mma.sync bf16 (3-term hi/lo split) =================
// Out[4096,128] = A[4096,8192] @ W[8192,128].  CTA tile 64m x 128n, K-chunk 32,
// double-buffered cp.async smem. Warp w: m-half = w&1, n-half = w>>1.
// smem per buffer: Ah 64x40bf16 (5120B), Al (+5120), Wh 128x40 (10240B, +10240), Wl (+20480). BUF=30720.
#define CONV_BUF 30720
#define CONV_SMEM (2 * CONV_BUF)
__global__ __launch_bounds__(128) void k_convmma(const float* __restrict__ biasX,
                                                 const float* __restrict__ biasY) {
    extern __shared__ __align__(16) char smem[];
    int t = threadIdx.x;
    int wid = t >> 5, l = t & 31;
    int mt = blockIdx.x, feat = blockIdx.y;
    uint32_t sb = smem_u32(smem);

    const __nv_bfloat16* Ah = g_Ah + (size_t)feat * NPTS * 8192 + (size_t)mt * 64 * 8192;
    const __nv_bfloat16* Al = g_Al + (size_t)feat * NPTS * 8192 + (size_t)mt * 64 * 8192;
    const __nv_bfloat16* Wh = g_Wh + (size_t)feat * 128 * 8192;
    const __nv_bfloat16* Wl = g_Wl + (size_t)feat * 128 * 8192;

    // issue cp.asyncs for one 32-wide K chunk into buffer `buf`
    auto load_tile = [&](int kt, int buf) {
        uint32_t base = sb + buf * CONV_BUF;
        #pragma unroll
        for (int i = 0; i < 12; i++) {
            int c = i * 128 + t;             // 1536 16B transfers
            const __nv_bfloat16* src;
            uint32_t moff; int local;
            if (i < 2)      { src = Ah; moff = 0;     local = c; }
            else if (i < 4) { src = Al; moff = 5120;  local = c - 256; }
            else if (i < 8) { src = Wh; moff = 10240; local = c - 512; }
            else            { src = Wl; moff = 20480; local = c - 1024; }
            int row = local >> 2, kp = local & 3;
            cp_async16(base + moff + row * 80 + kp * 16,
                       src + (size_t)row * 8192 + kt * 32 + kp * 8);
        }
        CP_COMMIT();
    };

    int wm = wid & 1, wn = wid >> 1;
    float acc[2][8][4];
    #pragma unroll
    for (int a = 0; a < 2; a++)
        #pragma unroll
        for (int b = 0; b < 8; b++)
            #pragma unroll
            for (int cc = 0; cc < 4; cc++) acc[a][b][cc] = 0.f;

    load_tile(0, 0);
    const int NK = 8192 / 32;
    for (int kt = 0; kt < NK; kt++) {
        int buf = kt & 1;
        if (kt + 1 < NK) { load_tile(kt + 1, buf ^ 1); CP_WAIT(1); }
        else             { CP_WAIT(0); }
        __syncthreads();
        uint32_t ab = sb + buf * CONV_BUF;
        #pragma unroll
        for (int k16 = 0; k16 < 2; k16++) {
            int kb2 = k16 * 32;              // col byte offset
            uint32_t ah[2][4], al[2][4];
            #pragma unroll
            for (int mf = 0; mf < 2; mf++) {
                int row = wm * 32 + mf * 16 + (l & 15);
                uint32_t colb = kb2 + (l >> 4) * 16;
                ldm_x4(ah[mf], ab + 0    + row * 80 + colb);
                ldm_x4(al[mf], ab + 5120 + row * 80 + colb);
            }
            uint32_t wh[4][4], wl[4][4];
            #pragma unroll
            for (int ng = 0; ng < 4; ng++) {
                int row = wn * 64 + ng * 16 + (l & 7) + (l >> 4) * 8;
                uint32_t colb = kb2 + ((l >> 3) & 1) * 16;
                ldm_x4(wh[ng], ab + 10240 + row * 80 + colb);
                ldm_x4(wl[ng], ab + 20480 + row * 80 + colb);
            }
            #pragma unroll
            for (int mf = 0; mf < 2; mf++)
                #pragma unroll
                for (int ng = 0; ng < 4; ng++) {
                    mma16816(acc[mf][2 * ng],     ah[mf], &wh[ng][0]);
                    mma16816(acc[mf][2 * ng],     al[mf], &wh[ng][0]);
                    mma16816(acc[mf][2 * ng],     ah[mf], &wl[ng][0]);
                    mma16816(acc[mf][2 * ng + 1], ah[mf], &wh[ng][2]);
                    mma16816(acc[mf][2 * ng + 1], al[mf], &wh[ng][2]);
                    mma16816(acc[mf][2 * ng + 1], ah[mf], &wl[ng][2]);
                }
        }
        __syncthreads();
    }

    const float* bias = feat ? biasY : biasX;
    float* out = g_conv[feat];
    #pragma unroll
    for (int mf = 0; mf < 2; mf++) {
        int r0 = mt * 64 + wm * 32 + mf * 16 + (l >> 2);
        #pragma unroll
        for (int nf = 0; nf < 8; nf++) {
            int col = wn * 64 + nf * 8 + (l & 3) * 2;
            out[(size_t)r0 * 128 + col]           = acc[mf][nf][0] + bias[col];
            out[(size_t)r0 * 128 + col + 1]       = acc[mf][nf][1] + bias[col + 1];
            out[(size_t)(r0 + 8) * 128 + col]     = acc[mf][nf][2] + bias[col];
            out[(size_t)(r0 + 8) * 128 + col + 1] = acc[mf][nf][3] + bias[col + 1];
        }
    }
}

// ================= SIMT GEMM (small mats): Out = In @ W.T + b =================
// flags: 1=relu, 2=head-layout store, 8=blockIdx.y selects weight (QKV)
template <bool WT>
__global__ __launch_bounds__(128) void k_gemm(int inId,
                                              const float* W0, const float* W1, const float* W2,
                                              const float* B0, const float* B1, const float* B2,
                                              int outId, int Kdim, int O, int flags) {
    __shared__ __align__(16) float InsT[16][64];
    __shared__ __align__(16) float Ws[16][128];
    int feat = blockIdx.z;
    int sel = (flags & 8) ? blockIdx.y : 0;
    const float* W = (sel == 0) ? W0 : (sel == 1) ? W1 : W2;
    const float* bias = (sel == 0) ? B0 : (sel == 1) ? B1 : B2;
    const float* In = resolve(inId, feat);
    float* Out = resolve((flags & 8) ? outId + sel : outId, feat);
    int t = threadIdx.x;
    int bm0 = blockIdx.x * 64;
    int bn0 = (flags & 8) ? 0 : blockIdx.y * 128;
    int tr = t >> 4, tc = t & 15;
    float acc[8][8];
    #pragma unroll
    for (int a = 0; a < 8; a++)
        #pragma unroll
        for (int b = 0; b < 8; b++) acc[a][b] = 0.f;

    for (int kb = 0; kb < Kdim; kb += 16) {
        __syncthreads();
        #pragma unroll
        for (int e = 0; e < 2; e++) {
            int f = t * 2 + e;
            int row = f >> 2;
            int k4 = (f & 3) * 4;
            float4 v = *(const float4*)&In[(size_t)(bm0 + row) * Kdim + kb + k4];
            InsT[k4 + 0][row] = v.x; InsT[k4 + 1][row] = v.y;
            InsT[k4 + 2][row] = v.z; InsT[k4 + 3][row] = v.w;
        }
        #pragma unroll
        for (int e = 0; e < 4; e++) {
            float4 v = *(const float4*)&W[(size_t)(bn0 + t) * Kdim + kb + e * 4];
            Ws[e * 4 + 0][t] = v.x; Ws[e * 4 + 1][t] = v.y;
            Ws[e * 4 + 2][t] = v.z; Ws[e * 4 + 3][t] = v.w;
        }
        __syncthreads();
        #pragma unroll
        for (int k = 0; k < 16; k++) {
            float a[8], w[8];
            *(float4*)&a[0] = *(const float4*)&InsT[k][tr * 8];
            *(float4*)&a[4] = *(const float4*)&InsT[k][tr * 8 + 4];
            *(float4*)&w[0] = *(const float4*)&Ws[k][tc * 8];
            *(float4*)&w[4] = *(const float4*)&Ws[k][tc * 8 + 4];
            #pragma unroll
            for (int ii = 0; ii < 8; ii++)
                #pragma unroll
                for (int jj = 0; jj < 8; jj++)
                    acc[ii][jj] = fmaf(a[ii], w[jj], acc[ii][jj]);
        }
    }
    #pragma unroll
    for (int ii = 0; ii < 8; ii++) {
        int n = bm0 + tr * 8 + ii;
        #pragma unroll
        for (int jj = 0; jj < 8; jj++) {
            int o = bn0 + tc * 8 + jj;
            float v = acc[ii][jj] + bias[o];
            if (flags & 1) v = fmaxf(v, 0.f);
            if (flags & 2) Out[((size_t)(o >> 5) * NPTS + n) * 32 + (o & 31)] = v;
            else           Out[(size_t)n * O + o] = v;
        }
    }
}

// ================= batch-norm =================
__global__ void k_bnstats() {
    __shared__ float ss[128], sq[128];
    int c = blockIdx.x, feat = blockIdx.y, t = threadIdx.x;
    float s = 0.f, q = 0.f;
    for (int r = t; r < NPTS; r += 128) {
        float v = g_conv[feat][(size_t)r * 128 + c];
        s += v; q = fmaf(v, v, q);
    }
    ss[t] = s; sq[t] = q;
    __syncthreads();
    for (int o = 64; o > 0; o >>= 1) {
        if (t < o) { ss[t] += ss[t + o]; sq[t] += sq[t + o]; }
        __syncthreads();
    }
    if (t == 0) {
        float m = ss[0] / 4096.f;
        float var = sq[0] / 4096.f - m * m;
        g_stats[feat][c] = m;
        g_stats[feat][128 + c] = rsqrtf(var + 1e-5f);
    }
}

__global__ void k_bnrelu(const float* __restrict__ gx, const float* __restrict__ bx,
                         const float* __restrict__ gy, const float* __restrict__ by) {
    int n = blockIdx.x, feat = blockIdx.y, c = threadIdx.x;
    const float* g = feat ? gy : gx;
    const float* b = feat ? by : bx;
    float v = (g_conv[feat][(size_t)n * 128 + c] - g_stats[feat][c]) * g_stats[feat][128 + c] * g[c] + b[c];
    g_feat[feat][(size_t)n * 128 + c] = fmaxf(v, 0.f);
}

// ================= h = feat + pos_encoding =================
__global__ void k_addpe(const float* __restrict__ pos) {
    int n = blockIdx.x, feat = blockIdx.y, t = threadIdx.x;
    float px = (pos[n * 3] - g_pstats[0]) * g_pstats[1];
    int i = t >> 1;
    float ang = px * expf(-0.14391156831212798f * (float)i);
    float pe = (t & 1) ? cosf(ang) : sinf(ang);
    g_h[feat][(size_t)n * 128 + t] = g_feat[feat][(size_t)n * 128 + t] + pe;
}

// ================= flash attention (thread-per-query) =================
__global__ __launch_bounds__(128) void k_attn() {
    __shared__ float Ks[1024], Vs[1024];
    int head = blockIdx.y, feat = blockIdx.z;
    int t = threadIdx.x;
    int qi = blockIdx.x * 128 + t;
    const float* qb = g_q[feat];
    const float* kb = g_k[feat];
    const float* vb = g_v[feat];
    const float4* qp = (const float4*)(qb + ((size_t)head * NPTS + qi) * 32);
    const float sc = 0.17677669529663687f;
    float Q[32], acc[32];
    #pragma unroll
    for (int d4 = 0; d4 < 8; d4++) {
        float4 v = qp[d4];
        Q[4 * d4 + 0] = v.x * sc; Q[4 * d4 + 1] = v.y * sc;
        Q[4 * d4 + 2] = v.z * sc; Q[4 * d4 + 3] = v.w * sc;
    }
    #pragma unroll
    for (int d = 0; d < 32; d++) acc[d] = 0.f;
    float m = -1e30f, l = 0.f;
    for (int kt = 0; kt < 128; kt++) {
        __syncthreads();
        const float4* kp = (const float4*)(kb + ((size_t)head * NPTS + kt * 32) * 32);
        const float4* vp = (const float4*)(vb + ((size_t)head * NPTS + kt * 32) * 32);
        ((float4*)Ks)[t] = kp[t]; ((float4*)Ks)[t + 128] = kp[t + 128];
        ((float4*)Vs)[t] = vp[t]; ((float4*)Vs)[t + 128] = vp[t + 128];
        __syncthreads();
        float sv[32];
        #pragma unroll
        for (int k = 0; k < 32; k++) {
            const float4* kr = (const float4*)(Ks + k * 32);
            float s0 = 0.f, s1 = 0.f, s2 = 0.f, s3 = 0.f;
            #pragma unroll
            for (int d4 = 0; d4 < 8; d4++) {
                float4 kk = kr[d4];
                s0 = fmaf(Q[4 * d4 + 0], kk.x, s0);
                s1 = fmaf(Q[4 * d4 + 1], kk.y, s1);
                s2 = fmaf(Q[4 * d4 + 2], kk.z, s2);
                s3 = fmaf(Q[4 * d4 + 3], kk.w, s3);
            }
            sv[k] = (s0 + s1) + (s2 + s3);
        }
        float tm = sv[0];
        #pragma unroll
        for (int k = 1; k < 32; k++) tm = fmaxf(tm, sv[k]);
        float mn = fmaxf(m, tm);
        float corr = fast_exp(m - mn);
        m = mn; l *= corr;
        #pragma unroll
        for (int d = 0; d < 32; d++) acc[d] *= corr;
        #pragma unroll
        for (int k = 0; k < 32; k++) {
            float p = fast_exp(sv[k] - m);
            l += p;
            const float4* vr = (const float4*)(Vs + k * 32);
            #pragma unroll
            for (int d4 = 0; d4 < 8; d4++) {
                float4 vv = vr[d4];
                acc[4 * d4 + 0] = fmaf(p, vv.x, acc[4 * d4 + 0]);
                acc[4 * d4 + 1] = fmaf(p, vv.y, acc[4 * d4 + 1]);
                acc[4 * d4 + 2] = fmaf(p, vv.z, acc[4 * d4 + 2]);
                acc[4 * d4 + 3] = fmaf(p, vv.w, acc[4 * d4 + 3]);
            }
        }
    }
    float inv = 1.f / l;
    float4* op = (float4*)(g_attn[feat] + (size_t)qi * 128 + head * 32);
    #pragma unroll
    for (int d4 = 0; d4 < 8; d4++) {
        float4 o;
        o.x = acc[4 * d4 + 0] * inv; o.y = acc[4 * d4 + 1] * inv;
        o.z = acc[4 * d4 + 2] * inv; o.w = acc[4 * d4 + 3] * inv;
        op[d4] = o;
    }
}

// ================= layernorm of (A + B) =================
__global__ void k_ln(int aId, int bId, int outId, const float* __restrict__ g,
                     const float* __restrict__ b) {
    __shared__ float rs[4], rq[4];
    int n = blockIdx.x, feat = blockIdx.y, t = threadIdx.x;
    const float* A = resolve(aId, feat);
    const float* B = resolve(bId, feat);
    float* O = resolve(outId, feat);
    float v = A[(size_t)n * 128 + t] + B[(size_t)n * 128 + t];
    float s = v, q = v * v;
    #pragma unroll
    for (int o = 16; o > 0; o >>= 1) {
        s += __shfl_xor_sync(0xffffffffu, s, o);
        q += __shfl_xor_sync(0xffffffffu, q, o);
    }
    int w = t >> 5;
    if ((t & 31) == 0) { rs[w] = s; rq[w] = q; }
    __syncthreads();
    s = rs[0] + rs[1] + rs[2] + rs[3];
    q = rq[0] + rq[1] + rq[2] + rq[3];
    float mean = s * (1.f / 128.f);
    float var = q * (1.f / 128.f) - mean * mean;
    O[(size_t)n * 128 + t] = (v - mean) * rsqrtf(var + 1e-5f) * g[t] + b[t];
}

// ================= final gating =================
__global__ void k_final(const float* __restrict__ x, const float* __restrict__ y,
                        float* __restrict__ out) {
    int i = blockIdx.x * 256 + threadIdx.x;
    float z = g_feat[0][i] + g_feat[1][i];
    float w = 1.f / (1.f + fast_exp(-z));
    out[i] = 2.f * (x[i] * w + y[i] * (1.f - w));
}

// ================= host orchestration =================
extern "C" void kernel_launch(void* const* d_in, const int* in_sizes, int n_in,
                              void* d_out, int out_size) {
    const float* x   = (const float*)d_in[0];
    const float* y   = (const float*)d_in[1];
    const float* pos = (const float*)d_in[2];
    const int*   nbr = (const int*)d_in[3];
    const float* Wx  = (const float*)d_in[5];
    const float* bx  = (const float*)d_in[6];
    const float* bxg = (const float*)d_in[7];
    const float* bxb = (const float*)d_in[8];
    const float* Wy  = (const float*)d_in[9];
    const float* by  = (const float*)d_in[10];
    const float* byg = (const float*)d_in[11];
    const float* byb = (const float*)d_in[12];
    const float* Wq  = (const float*)d_in[13];
    const float* bq  = (const float*)d_in[14];
    const float* Wk  = (const float*)d_in[15];
    const float* bk  = (const float*)d_in[16];
    const float* Wv  = (const float*)d_in[17];
    const float* bv  = (const float*)d_in[18];
    const float* Wo  = (const float*)d_in[19];
    const float* bo  = (const float*)d_in[20];
    const float* l1g = (const float*)d_in[21];
    const float* l1b = (const float*)d_in[22];
    const float* W1  = (const float*)d_in[23];
    const float* b1  = (const float*)d_in[24];
    const float* W2  = (const float*)d_in[25];
    const float* b2  = (const float*)d_in[26];
    const float* l2g = (const float*)d_in[27];
    const float* l2b = (const float*)d_in[28];
    float* out = (float*)d_out;

    cudaFuncSetAttribute(k_convmma, cudaFuncAttributeMaxDynamicSharedMemorySize, CONV_SMEM);

    k_posstats<<<1, 256>>>(pos);
    k_prepW<<<dim3(1024, 2), 128>>>(Wx, Wy);
    k_stageA<<<dim3(4096, 2), 128>>>(x, y, pos, nbr);
    k_convmma<<<dim3(64, 2), 128, CONV_SMEM>>>(bx, by);
    k_bnstats<<<dim3(128, 2), 128>>>();
    k_bnrelu<<<dim3(4096, 2), 128>>>(bxg, bxb, byg, byb);

    // transformer block (both features fused via grid.z)
    k_addpe<<<dim3(4096, 2), 128>>>(pos);
    k_gemm<true><<<dim3(64, 3, 2), 128>>>(4, Wq, Wk, Wv, bq, bk, bv, 5, 128, 128, 2 | 8);
    k_attn<<<dim3(32, 4, 2), 128>>>();
    k_gemm<true><<<dim3(64, 1, 2), 128>>>(8, Wo, Wo, Wo, bo, bo, bo, 9, 128, 128, 0);
    k_ln<<<dim3(4096, 2), 128>>>(2, 9, 10, l1g, l1b);
    k_gemm<true><<<dim3(64, 4, 2), 128>>>(10, W1, W1, W1, b1, b1, b1, 11, 128, 512, 1);
    k_gemm<true><<<dim3(64, 1, 2), 128>>>(11, W2, W2, W2, b2, b2, b2, 4, 512, 128, 0);
    k_ln<<<dim3(4096, 2), 128>>>(10, 4, 2, l2g, l2b);

    k_final<<<2048, 256>>>(x, y, out);
}

// round 14
// speedup vs baseline: 2.8053x; 1.4790x over previous
#include <cuda_runtime.h>
#include <cuda_bf16.h>
#include <math.h>
#include <stdint.h>

// ================= scratch (device globals; no allocation APIs) =================
#define NPTS 4096
__device__ __nv_bfloat16 g_Ah[2ull * NPTS * 8192];
__device__ __nv_bfloat16 g_Al[2ull * NPTS * 8192];
__device__ __nv_bfloat16 g_Wh[2ull * 128 * 8192];
__device__ __nv_bfloat16 g_Wl[2ull * 128 * 8192];
__device__ float g_conv[2][NPTS * 128];
__device__ float g_convB[2][NPTS * 128];
__device__ float g_feat[2][NPTS * 128];
__device__ float g_h[2][NPTS * 128];
__device__ float g_attn[2][NPTS * 128];
__device__ float g_op[2][NPTS * 128];
__device__ float g_h1[2][NPTS * 128];
__device__ float g_ffh[2][NPTS * 512];
// bf16 hi/lo QKV for tensor attention.  q,k: [h][n][32]; v: [h][d][n]
__device__ __nv_bfloat16 g_qh[2ull * 524288], g_ql[2ull * 524288];
__device__ __nv_bfloat16 g_kh[2ull * 524288], g_kl[2ull * 524288];
__device__ __nv_bfloat16 g_vh[2ull * 524288], g_vl[2ull * 524288];
__device__ float g_stats[2][256];
__device__ float g_pstats[2];

__device__ __forceinline__ float* resolve(int id, int feat) {
    switch (id) {
        case 1:  return g_conv[feat];
        case 2:  return g_feat[feat];
        case 4:  return g_h[feat];
        case 8:  return g_attn[feat];
        case 9:  return g_op[feat];
        case 10: return g_h1[feat];
        default: return g_ffh[feat];
    }
}

// ================= baseline-PTX helpers (sm_103-safe) =================
static __device__ __forceinline__ uint32_t smem_u32(const void* p) {
    uint32_t a;
    asm("{ .reg .u64 t; cvta.to.shared.u64 t, %1; cvt.u32.u64 %0, t; }" : "=r"(a) : "l"(p));
    return a;
}
static __device__ __forceinline__ void cp_async16(uint32_t dst, const void* src) {
    asm volatile("cp.async.cg.shared.global [%0], [%1], 16;" :: "r"(dst), "l"(src) : "memory");
}
#define CP_COMMIT() asm volatile("cp.async.commit_group;" ::: "memory")
#define CP_WAIT(n)  asm volatile("cp.async.wait_group %0;" :: "n"(n) : "memory")

static __device__ __forceinline__ void ldm_x4(uint32_t* r, uint32_t addr) {
    asm volatile("ldmatrix.sync.aligned.m8n8.x4.shared.b16 {%0,%1,%2,%3}, [%4];"
                 : "=r"(r[0]), "=r"(r[1]), "=r"(r[2]), "=r"(r[3]) : "r"(addr));
}
static __device__ __forceinline__ void mma16816(float* c, const uint32_t* a, const uint32_t* b) {
    asm volatile("mma.sync.aligned.m16n8k16.row.col.f32.bf16.bf16.f32 "
                 "{%0,%1,%2,%3}, {%4,%5,%6,%7}, {%8,%9}, {%0,%1,%2,%3};"
                 : "+f"(c[0]), "+f"(c[1]), "+f"(c[2]), "+f"(c[3])
                 : "r"(a[0]), "r"(a[1]), "r"(a[2]), "r"(a[3]), "r"(b[0]), "r"(b[1]));
}

// fast exp on FMA pipe
__device__ __forceinline__ float fast_exp(float x) {
    float t = x * 1.4426950408889634f;
    t = fmaxf(t, -126.0f);
    float fi = floorf(t);
    float f  = t - fi;
    float r  = 1.5403530393381606e-4f;
    r = fmaf(r, f, 1.3333558146428443e-3f);
    r = fmaf(r, f, 9.6181291076284770e-3f);
    r = fmaf(r, f, 5.5504108664821580e-2f);
    r = fmaf(r, f, 2.4022650695910070e-1f);
    r = fmaf(r, f, 6.9314718055994530e-1f);
    r = fmaf(r, f, 1.0f);
    return r * __int_as_float(((int)fi + 127) << 23);
}

static __device__ __forceinline__ void pack_hilo(float a, float b, uint32_t& h, uint32_t& lo) {
    __nv_bfloat162 hh = __floats2bfloat162_rn(a, b);
    float2 hf = __bfloat1622float2(hh);
    __nv_bfloat162 ll = __floats2bfloat162_rn(a - hf.x, b - hf.y);
    h  = *reinterpret_cast<uint32_t*>(&hh);
    lo = *reinterpret_cast<uint32_t*>(&ll);
}

// ================= pos stats =================
__global__ void k_posstats(const float* __restrict__ pos) {
    __shared__ float ss[256], sq[256];
    int t = threadIdx.x;
    float s = 0.f, q = 0.f;
    for (int i = t; i < NPTS; i += 256) {
        float v = pos[i * 3];
        s += v; q = fmaf(v, v, q);
    }
    ss[t] = s; sq[t] = q;
    __syncthreads();
    for (int o = 128; o > 0; o >>= 1) {
        if (t < o) { ss[t] += ss[t + o]; sq[t] += sq[t + o]; }
        __syncthreads();
    }
    if (t == 0) {
        float m  = ss[0] / 4096.f;
        float sd = sqrtf(fmaxf((sq[0] - 4096.f * m * m) / 4095.f, 0.f));
        g_pstats[0] = m;
        g_pstats[1] = 1.f / (sd + 1e-8f);
    }
}

// ================= weight prep: transpose + bf16 hi/lo split -> W[o][k] =================
__global__ void k_prepW(const float* __restrict__ Wx, const float* __restrict__ Wy) {
    int feat = blockIdx.y;
    const float* W = feat ? Wy : Wx;
    __nv_bfloat16* Wh = g_Wh + (size_t)feat * 128 * 8192;
    __nv_bfloat16* Wl = g_Wl + (size_t)feat * 128 * 8192;
    int o = threadIdx.x;
    int k8 = blockIdx.x * 8;
    #pragma unroll
    for (int j = 0; j < 8; j++) {
        float v = W[(size_t)(k8 + j) * 128 + o];
        __nv_bfloat16 h = __float2bfloat16(v);
        __nv_bfloat16 l = __float2bfloat16(v - __bfloat162float(h));
        Wh[(size_t)o * 8192 + k8 + j] = h;
        Wl[(size_t)o * 8192 + k8 + j] = l;
    }
}

// ================= cconv stage A: scatter into A[n][64cells][128c], bf16 hi/lo out =================
__global__ __launch_bounds__(128) void k_stageA(const float* __restrict__ x,
                                                const float* __restrict__ y,
                                                const float* __restrict__ pos,
                                                const int* __restrict__ nbr) {
    __shared__ float A[64 * 128];
    __shared__ float wgt[80][8];
    __shared__ int   cel[80][8];
    __shared__ int   jl[80];
    __shared__ int   vld[80];
    int i = blockIdx.x;
    int feat = blockIdx.y;
    const float* src = feat ? y : x;
    int t = threadIdx.x;
    for (int u = t; u < 64 * 128; u += 128) A[u] = 0.f;
    if (t < 80) {
        int j = nbr[i * 80 + t];
        jl[t] = j;
        const float R = 0.1125f;
        float rx = (pos[3 * j + 0] - pos[3 * i + 0]) / R;
        float ry = (pos[3 * j + 1] - pos[3 * i + 1]) / R;
        float rz = (pos[3 * j + 2] - pos[3 * i + 2]) / R;
        float r2 = rx * rx + ry * ry + rz * rz;
        float win = 0.f;
        if (j != i) {
            float w1 = 1.f - r2;
            win = fminf(fmaxf(w1 * w1 * w1, 0.f), 1.f);
        }
        vld[t] = (win > 0.f) ? 1 : 0;
        float nrm  = sqrtf(fmaxf(r2, 1e-12f));
        float linf = fmaxf(fmaxf(fabsf(rx), fabsf(ry)), fabsf(rz));
        linf = fmaxf(linf, 1e-9f);
        float sc = nrm / linf;
        float gx = fminf(fmaxf(fmaf(rx * sc, 1.5f, 1.5f), 0.f), 3.f);
        float gy = fminf(fmaxf(fmaf(ry * sc, 1.5f, 1.5f), 0.f), 3.f);
        float gz = fminf(fmaxf(fmaf(rz * sc, 1.5f, 1.5f), 0.f), 3.f);
        float fx = fminf(floorf(gx), 2.f);
        float fy = fminf(floorf(gy), 2.f);
        float fz = fminf(floorf(gz), 2.f);
        float tx = gx - fx, ty = gy - fy, tz = gz - fz;
        int base = (int)fx * 16 + (int)fy * 4 + (int)fz;
        #pragma unroll
        for (int dx = 0; dx < 2; dx++)
            #pragma unroll
            for (int dy = 0; dy < 2; dy++)
                #pragma unroll
                for (int dz = 0; dz < 2; dz++) {
                    float cw = (dx ? tx : 1.f - tx) * (dy ? ty : 1.f - ty) * (dz ? tz : 1.f - tz);
                    int q = dx * 4 + dy * 2 + dz;
                    wgt[t][q] = win * cw;
                    cel[t][q] = base + dx * 16 + dy * 4 + dz;
                }
    }
    __syncthreads();
    int c = t;
    for (int nb = 0; nb < 80; nb++) {
        if (!vld[nb]) continue;
        float f = src[(size_t)jl[nb] * 128 + c];
        #pragma unroll
        for (int q = 0; q < 8; q++)
            A[cel[nb][q] * 128 + c] += wgt[nb][q] * f;
    }
    __syncthreads();
    __nv_bfloat16* dh = g_Ah + (size_t)feat * NPTS * 8192 + (size_t)i * 8192;
    __nv_bfloat16* dl = g_Al + (size_t)feat * NPTS * 8192 + (size_t)i * 8192;
    for (int u = t; u < 8192; u += 128) {
        float v = A[u];
        __nv_bfloat16 h = __float2bfloat16(v);
        dh[u] = h;
        dl[u] = __float2bfloat16(v - __bfloat162float(h));
    }
}

// ================= conv GEMM via mma.sync bf16 (3-term hi/lo split, split-K=2) =================
#define CONV_BUF 30720
#define CONV_SMEM (2 * CONV_BUF)
__global__ __launch_bounds__(128) void k_convmma(const float* __restrict__ biasX,
                                                 const float* __restrict__ biasY) {
    extern __shared__ __align__(16) char smem[];
    int t = threadIdx.x;
    int wid = t >> 5, l = t & 31;
    int mt = blockIdx.x, feat = blockIdx.y, kz = blockIdx.z;
    uint32_t sb = smem_u32(smem);

    const __nv_bfloat16* Ah = g_Ah + (size_t)feat * NPTS * 8192 + (size_t)mt * 64 * 8192;
    const __nv_bfloat16* Al = g_Al + (size_t)feat * NPTS * 8192 + (size_t)mt * 64 * 8192;
    const __nv_bfloat16* Wh = g_Wh + (size_t)feat * 128 * 8192;
    const __nv_bfloat16* Wl = g_Wl + (size_t)feat * 128 * 8192;

    auto load_tile = [&](int kt, int buf) {
        uint32_t base = sb + buf * CONV_BUF;
        #pragma unroll
        for (int i = 0; i < 12; i++) {
            int c = i * 128 + t;
            const __nv_bfloat16* src;
            uint32_t moff; int local;
            if (i < 2)      { src = Ah; moff = 0;     local = c; }
            else if (i < 4) { src = Al; moff = 5120;  local = c - 256; }
            else if (i < 8) { src = Wh; moff = 10240; local = c - 512; }
            else            { src = Wl; moff = 20480; local = c - 1024; }
            int row = local >> 2, kp = local & 3;
            cp_async16(base + moff + row * 80 + kp * 16,
                       src + (size_t)row * 8192 + kt * 32 + kp * 8);
        }
        CP_COMMIT();
    };

    int wm = wid & 1, wn = wid >> 1;
    float acc[2][8][4];
    #pragma unroll
    for (int a = 0; a < 2; a++)
        #pragma unroll
        for (int b = 0; b < 8; b++)
            #pragma unroll
            for (int cc = 0; cc < 4; cc++) acc[a][b][cc] = 0.f;

    int kt0 = kz * 128;
    load_tile(kt0, 0);
    for (int kk = 0; kk < 128; kk++) {
        int kt = kt0 + kk;
        int buf = kk & 1;
        if (kk + 1 < 128) { load_tile(kt + 1, buf ^ 1); CP_WAIT(1); }
        else              { CP_WAIT(0); }
        __syncthreads();
        uint32_t ab = sb + buf * CONV_BUF;
        #pragma unroll
        for (int k16 = 0; k16 < 2; k16++) {
            int kb2 = k16 * 32;
            uint32_t ah[2][4], al[2][4];
            #pragma unroll
            for (int mf = 0; mf < 2; mf++) {
                int row = wm * 32 + mf * 16 + (l & 15);
                uint32_t colb = kb2 + (l >> 4) * 16;
                ldm_x4(ah[mf], ab + 0    + row * 80 + colb);
                ldm_x4(al[mf], ab + 5120 + row * 80 + colb);
            }
            uint32_t wh[4][4], wl[4][4];
            #pragma unroll
            for (int ng = 0; ng < 4; ng++) {
                int row = wn * 64 + ng * 16 + (l & 7) + (l >> 4) * 8;
                uint32_t colb = kb2 + ((l >> 3) & 1) * 16;
                ldm_x4(wh[ng], ab + 10240 + row * 80 + colb);
                ldm_x4(wl[ng], ab + 20480 + row * 80 + colb);
            }
            #pragma unroll
            for (int mf = 0; mf < 2; mf++)
                #pragma unroll
                for (int ng = 0; ng < 4; ng++) {
                    mma16816(acc[mf][2 * ng],     ah[mf], &wh[ng][0]);
                    mma16816(acc[mf][2 * ng],     al[mf], &wh[ng][0]);
                    mma16816(acc[mf][2 * ng],     ah[mf], &wl[ng][0]);
                    mma16816(acc[mf][2 * ng + 1], ah[mf], &wh[ng][2]);
                    mma16816(acc[mf][2 * ng + 1], al[mf], &wh[ng][2]);
                    mma16816(acc[mf][2 * ng + 1], ah[mf], &wl[ng][2]);
                }
        }
        __syncthreads();
    }

    const float* bias = feat ? biasY : biasX;
    float* out = kz ? g_convB[feat] : g_conv[feat];
    #pragma unroll
    for (int mf = 0; mf < 2; mf++) {
        int r0 = mt * 64 + wm * 32 + mf * 16 + (l >> 2);
        #pragma unroll
        for (int nf = 0; nf < 8; nf++) {
            int col = wn * 64 + nf * 8 + (l & 3) * 2;
            float b0 = kz ? 0.f : bias[col];
            float b1 = kz ? 0.f : bias[col + 1];
            out[(size_t)r0 * 128 + col]           = acc[mf][nf][0] + b0;
            out[(size_t)r0 * 128 + col + 1]       = acc[mf][nf][1] + b1;
            out[(size_t)(r0 + 8) * 128 + col]     = acc[mf][nf][2] + b0;
            out[(size_t)(r0 + 8) * 128 + col + 1] = acc[mf][nf][3] + b1;
        }
    }
}

// ================= SIMT GEMM: Out = In @ W.T + b =================
// flags: 1=relu, 8=blockIdx.y selects weight, 16=bf16 hi/lo QKV store
template <bool WT>
__global__ __launch_bounds__(128) void k_gemm(int inId,
                                              const float* W0, const float* W1, const float* W2,
                                              const float* B0, const float* B1, const float* B2,
                                              int outId, int Kdim, int O, int flags) {
    __shared__ __align__(16) float InsT[16][64];
    __shared__ __align__(16) float Ws[16][128];
    int feat = blockIdx.z;
    int sel = (flags & 8) ? blockIdx.y : 0;
    const float* W = (sel == 0) ? W0 : (sel == 1) ? W1 : W2;
    const float* bias = (sel == 0) ? B0 : (sel == 1) ? B1 : B2;
    const float* In = resolve(inId, feat);
    float* Out = resolve(outId, feat);
    int t = threadIdx.x;
    int bm0 = blockIdx.x * 64;
    int bn0 = (flags & 8) ? 0 : blockIdx.y * 128;
    int tr = t >> 4, tc = t & 15;
    float acc[8][8];
    #pragma unroll
    for (int a = 0; a < 8; a++)
        #pragma unroll
        for (int b = 0; b < 8; b++) acc[a][b] = 0.f;

    for (int kb = 0; kb < Kdim; kb += 16) {
        __syncthreads();
        #pragma unroll
        for (int e = 0; e < 2; e++) {
            int f = t * 2 + e;
            int row = f >> 2;
            int k4 = (f & 3) * 4;
            float4 v = *(const float4*)&In[(size_t)(bm0 + row) * Kdim + kb + k4];
            InsT[k4 + 0][row] = v.x; InsT[k4 + 1][row] = v.y;
            InsT[k4 + 2][row] = v.z; InsT[k4 + 3][row] = v.w;
        }
        #pragma unroll
        for (int e = 0; e < 4; e++) {
            float4 v = *(const float4*)&W[(size_t)(bn0 + t) * Kdim + kb + e * 4];
            Ws[e * 4 + 0][t] = v.x; Ws[e * 4 + 1][t] = v.y;
            Ws[e * 4 + 2][t] = v.z; Ws[e * 4 + 3][t] = v.w;
        }
        __syncthreads();
        #pragma unroll
        for (int k = 0; k < 16; k++) {
            float a[8], w[8];
            *(float4*)&a[0] = *(const float4*)&InsT[k][tr * 8];
            *(float4*)&a[4] = *(const float4*)&InsT[k][tr * 8 + 4];
            *(float4*)&w[0] = *(const float4*)&Ws[k][tc * 8];
            *(float4*)&w[4] = *(const float4*)&Ws[k][tc * 8 + 4];
            #pragma unroll
            for (int ii = 0; ii < 8; ii++)
                #pragma unroll
                for (int jj = 0; jj < 8; jj++)
                    acc[ii][jj] = fmaf(a[ii], w[jj], acc[ii][jj]);
        }
    }
    #pragma unroll
    for (int ii = 0; ii < 8; ii++) {
        int n = bm0 + tr * 8 + ii;
        #pragma unroll
        for (int jj = 0; jj < 8; jj++) {
            int o = bn0 + tc * 8 + jj;
            float v = acc[ii][jj] + bias[o];
            if (flags & 16) {
                // bf16 hi/lo QKV emission
                __nv_bfloat16* dh; __nv_bfloat16* dl; size_t idx;
                int head = o >> 5, d = o & 31;
                if (sel == 0) {
                    v *= 0.17677669529663687f;   // 1/sqrt(32)
                    dh = g_qh; dl = g_ql;
                    idx = (size_t)feat * 524288 + (size_t)head * 131072 + (size_t)n * 32 + d;
                } else if (sel == 1) {
                    dh = g_kh; dl = g_kl;
                    idx = (size_t)feat * 524288 + (size_t)head * 131072 + (size_t)n * 32 + d;
                } else {
                    dh = g_vh; dl = g_vl;
                    idx = (size_t)feat * 524288 + (size_t)head * 131072 + (size_t)d * 4096 + n;
                }
                __nv_bfloat16 h = __float2bfloat16(v);
                dh[idx] = h;
                dl[idx] = __float2bfloat16(v - __bfloat162float(h));
            } else {
                if (flags & 1) v = fmaxf(v, 0.f);
                Out[(size_t)n * O + o] = v;
            }
        }
    }
}

// ================= batch-norm (sums both split-K buffers) =================
__global__ void k_bnstats() {
    __shared__ float ss[128], sq[128];
    int c = blockIdx.x, feat = blockIdx.y, t = threadIdx.x;
    float s = 0.f, q = 0.f;
    for (int r = t; r < NPTS; r += 128) {
        float v = g_conv[feat][(size_t)r * 128 + c] + g_convB[feat][(size_t)r * 128 + c];
        s += v; q = fmaf(v, v, q);
    }
    ss[t] = s; sq[t] = q;
    __syncthreads();
    for (int o = 64; o > 0; o >>= 1) {
        if (t < o) { ss[t] += ss[t + o]; sq[t] += sq[t + o]; }
        __syncthreads();
    }
    if (t == 0) {
        float m = ss[0] / 4096.f;
        float var = sq[0] / 4096.f - m * m;
        g_stats[feat][c] = m;
        g_stats[feat][128 + c] = rsqrtf(var + 1e-5f);
    }
}

__global__ void k_bnrelu(const float* __restrict__ gx, const float* __restrict__ bx,
                         const float* __restrict__ gy, const float* __restrict__ by) {
    int n = blockIdx.x, feat = blockIdx.y, c = threadIdx.x;
    const float* g = feat ? gy : gx;
    const float* b = feat ? by : bx;
    float v0 = g_conv[feat][(size_t)n * 128 + c] + g_convB[feat][(size_t)n * 128 + c];
    float v = (v0 - g_stats[feat][c]) * g_stats[feat][128 + c] * g[c] + b[c];
    g_feat[feat][(size_t)n * 128 + c] = fmaxf(v, 0.f);
}

// ================= h = feat + pos_encoding =================
__global__ void k_addpe(const float* __restrict__ pos) {
    int n = blockIdx.x, feat = blockIdx.y, t = threadIdx.x;
    float px = (pos[n * 3] - g_pstats[0]) * g_pstats[1];
    int i = t >> 1;
    float ang = px * expf(-0.14391156831212798f * (float)i);
    float pe = (t & 1) ? cosf(ang) : sinf(ang);
    g_h[feat][(size_t)n * 128 + t] = g_feat[feat][(size_t)n * 128 + t] + pe;
}

// ================= flash attention via mma.sync bf16 =================
// CTA: 128 queries, one (head, feat). 4 warps x 32 queries. 32-key chunks, double buffered.
// smem: qh[128x80]@0, ql@10240, per-buf {kh@0,kl@2560,vh@5120,vl@7680} @ 20480+buf*10240.
__global__ __launch_bounds__(128) void k_attn_mma() {
    __shared__ __align__(16) char sm[40960];
    int t = threadIdx.x, wid = t >> 5, l = t & 31;
    int qt = blockIdx.x, head = blockIdx.y, feat = blockIdx.z;
    uint32_t sb = smem_u32(sm);

    const __nv_bfloat16* gqh = g_qh + (size_t)feat * 524288 + (size_t)head * 131072;
    const __nv_bfloat16* gql = g_ql + (size_t)feat * 524288 + (size_t)head * 131072;
    const __nv_bfloat16* gkh = g_kh + (size_t)feat * 524288 + (size_t)head * 131072;
    const __nv_bfloat16* gkl = g_kl + (size_t)feat * 524288 + (size_t)head * 131072;
    const __nv_bfloat16* gvh = g_vh + (size_t)feat * 524288 + (size_t)head * 131072;
    const __nv_bfloat16* gvl = g_vl + (size_t)feat * 524288 + (size_t)head * 131072;

    // load Q tile (128 x 32) hi/lo into smem, stride 80B
    #pragma unroll
    for (int i = 0; i < 4; i++) {
        int c = i * 128 + t;
        int row = c >> 2, cc = c & 3;
        size_t gidx = (size_t)(qt * 128 + row) * 32 + cc * 8;
        *(uint4*)(sm + row * 80 + cc * 16)         = *(const uint4*)(gqh + gidx);
        *(uint4*)(sm + 10240 + row * 80 + cc * 16) = *(const uint4*)(gql + gidx);
    }

    auto load_kv = [&](int ch, int buf) {
        uint32_t base = sb + 20480 + buf * 10240;
        #pragma unroll
        for (int i = 0; i < 4; i++) {
            int c = i * 128 + t;
            int which = c >> 7, local = c & 127;
            int row = local >> 2, cc = local & 3;
            const __nv_bfloat16* src;
            uint32_t off;
            size_t gidx;
            if (which == 0)      { src = gkh; off = 0;    gidx = (size_t)(ch * 32 + row) * 32 + cc * 8; }
            else if (which == 1) { src = gkl; off = 2560; gidx = (size_t)(ch * 32 + row) * 32 + cc * 8; }
            else if (which == 2) { src = gvh; off = 5120; gidx = (size_t)row * 4096 + ch * 32 + cc * 8; }
            else                 { src = gvl; off = 7680; gidx = (size_t)row * 4096 + ch * 32 + cc * 8; }
            cp_async16(base + off + row * 80 + cc * 16, src + gidx);
        }
        CP_COMMIT();
    };

    load_kv(0, 0);
    __syncthreads();

    // Q fragments (A layout, proven pattern)
    uint32_t qah[2][2][4], qal[2][2][4];
    #pragma unroll
    for (int mf = 0; mf < 2; mf++)
        #pragma unroll
        for (int ks = 0; ks < 2; ks++) {
            int row = wid * 32 + mf * 16 + (l & 15);
            uint32_t colb = ks * 32 + (l >> 4) * 16;
            ldm_x4(qah[mf][ks], sb + row * 80 + colb);
            ldm_x4(qal[mf][ks], sb + 10240 + row * 80 + colb);
        }

    float o[2][4][4];
    #pragma unroll
    for (int a = 0; a < 2; a++)
        #pragma unroll
        for (int b = 0; b < 4; b++)
            #pragma unroll
            for (int c = 0; c < 4; c++) o[a][b][c] = 0.f;
    float mrow[2][2] = {{-1e30f, -1e30f}, {-1e30f, -1e30f}};
    float lrow[2][2] = {{0.f, 0.f}, {0.f, 0.f}};

    const int NCH = 128;
    for (int ch = 0; ch < NCH; ch++) {
        int buf = ch & 1;
        if (ch + 1 < NCH) { load_kv(ch + 1, buf ^ 1); CP_WAIT(1); }
        else              { CP_WAIT(0); }
        __syncthreads();
        uint32_t kb = sb + 20480 + buf * 10240;

        // K fragments (B layout)
        uint32_t kbh[2][2][4], kbl[2][2][4];
        #pragma unroll
        for (int ng = 0; ng < 2; ng++)
            #pragma unroll
            for (int ks = 0; ks < 2; ks++) {
                int row = ng * 16 + (l & 7) + (l >> 4) * 8;
                uint32_t colb = ks * 32 + ((l >> 3) & 1) * 16;
                ldm_x4(kbh[ng][ks], kb + row * 80 + colb);
                ldm_x4(kbl[ng][ks], kb + 2560 + row * 80 + colb);
            }
        // V fragments (B layout; rows = d)
        uint32_t vbh[2][2][4], vbl[2][2][4];
        #pragma unroll
        for (int g = 0; g < 2; g++)
            #pragma unroll
            for (int ks = 0; ks < 2; ks++) {
                int row = g * 16 + (l & 7) + (l >> 4) * 8;
                uint32_t colb = ks * 32 + ((l >> 3) & 1) * 16;
                ldm_x4(vbh[g][ks], kb + 5120 + row * 80 + colb);
                ldm_x4(vbl[g][ks], kb + 7680 + row * 80 + colb);
            }

        #pragma unroll
        for (int mf = 0; mf < 2; mf++) {
            float s[4][4];
            #pragma unroll
            for (int n = 0; n < 4; n++)
                #pragma unroll
                for (int c = 0; c < 4; c++) s[n][c] = 0.f;
            #pragma unroll
            for (int ng = 0; ng < 2; ng++)
                #pragma unroll
                for (int ks = 0; ks < 2; ks++) {
                    mma16816(s[2 * ng],     qah[mf][ks], &kbh[ng][ks][0]);
                    mma16816(s[2 * ng],     qal[mf][ks], &kbh[ng][ks][0]);
                    mma16816(s[2 * ng],     qah[mf][ks], &kbl[ng][ks][0]);
                    mma16816(s[2 * ng + 1], qah[mf][ks], &kbh[ng][ks][2]);
                    mma16816(s[2 * ng + 1], qal[mf][ks], &kbh[ng][ks][2]);
                    mma16816(s[2 * ng + 1], qah[mf][ks], &kbl[ng][ks][2]);
                }
            // online softmax: rows r (c0,c1) and r+8 (c2,c3)
            float cm0 = fmaxf(fmaxf(s[0][0], s[0][1]), fmaxf(s[1][0], s[1][1]));
            cm0 = fmaxf(cm0, fmaxf(fmaxf(s[2][0], s[2][1]), fmaxf(s[3][0], s[3][1])));
            float cm1 = fmaxf(fmaxf(s[0][2], s[0][3]), fmaxf(s[1][2], s[1][3]));
            cm1 = fmaxf(cm1, fmaxf(fmaxf(s[2][2], s[2][3]), fmaxf(s[3][2], s[3][3])));
            cm0 = fmaxf(cm0, __shfl_xor_sync(0xffffffffu, cm0, 1));
            cm0 = fmaxf(cm0, __shfl_xor_sync(0xffffffffu, cm0, 2));
            cm1 = fmaxf(cm1, __shfl_xor_sync(0xffffffffu, cm1, 1));
            cm1 = fmaxf(cm1, __shfl_xor_sync(0xffffffffu, cm1, 2));
            float nm0 = fmaxf(mrow[mf][0], cm0);
            float nm1 = fmaxf(mrow[mf][1], cm1);
            float cr0 = fast_exp(mrow[mf][0] - nm0);
            float cr1 = fast_exp(mrow[mf][1] - nm1);
            mrow[mf][0] = nm0; mrow[mf][1] = nm1;
            lrow[mf][0] *= cr0; lrow[mf][1] *= cr1;
            #pragma unroll
            for (int nd = 0; nd < 4; nd++) {
                o[mf][nd][0] *= cr0; o[mf][nd][1] *= cr0;
                o[mf][nd][2] *= cr1; o[mf][nd][3] *= cr1;
            }
            uint32_t pah[2][4], pal[2][4];
            #pragma unroll
            for (int ks = 0; ks < 2; ks++) {
                int n0 = 2 * ks, n1 = 2 * ks + 1;
                float p00 = fast_exp(s[n0][0] - nm0), p01 = fast_exp(s[n0][1] - nm0);
                float p02 = fast_exp(s[n0][2] - nm1), p03 = fast_exp(s[n0][3] - nm1);
                float p10 = fast_exp(s[n1][0] - nm0), p11 = fast_exp(s[n1][1] - nm0);
                float p12 = fast_exp(s[n1][2] - nm1), p13 = fast_exp(s[n1][3] - nm1);
                lrow[mf][0] += (p00 + p01) + (p10 + p11);
                lrow[mf][1] += (p02 + p03) + (p12 + p13);
                pack_hilo(p00, p01, pah[ks][0], pal[ks][0]);
                pack_hilo(p02, p03, pah[ks][1], pal[ks][1]);
                pack_hilo(p10, p11, pah[ks][2], pal[ks][2]);
                pack_hilo(p12, p13, pah[ks][3], pal[ks][3]);
            }
            #pragma unroll
            for (int g = 0; g < 2; g++)
                #pragma unroll
                for (int ks = 0; ks < 2; ks++) {
                    mma16816(o[mf][2 * g],     pah[ks], &vbh[g][ks][0]);
                    mma16816(o[mf][2 * g],     pal[ks], &vbh[g][ks][0]);
                    mma16816(o[mf][2 * g],     pah[ks], &vbl[g][ks][0]);
                    mma16816(o[mf][2 * g + 1], pah[ks], &vbh[g][ks][2]);
                    mma16816(o[mf][2 * g + 1], pal[ks], &vbh[g][ks][2]);
                    mma16816(o[mf][2 * g + 1], pah[ks], &vbl[g][ks][2]);
                }
        }
        __syncthreads();
    }

    // finalize: quad-reduce l, normalize, store
    #pragma unroll
    for (int mf = 0; mf < 2; mf++) {
        float l0 = lrow[mf][0], l1 = lrow[mf][1];
        l0 += __shfl_xor_sync(0xffffffffu, l0, 1);
        l0 += __shfl_xor_sync(0xffffffffu, l0, 2);
        l1 += __shfl_xor_sync(0xffffffffu, l1, 1);
        l1 += __shfl_xor_sync(0xffffffffu, l1, 2);
        float i0 = 1.f / l0, i1 = 1.f / l1;
        int r0 = qt * 128 + wid * 32 + mf * 16 + (l >> 2);
        #pragma unroll
        for (int nd = 0; nd < 4; nd++) {
            int col = head * 32 + nd * 8 + (l & 3) * 2;
            g_attn[feat][(size_t)r0 * 128 + col]           = o[mf][nd][0] * i0;
            g_attn[feat][(size_t)r0 * 128 + col + 1]       = o[mf][nd][1] * i0;
            g_attn[feat][(size_t)(r0 + 8) * 128 + col]     = o[mf][nd][2] * i1;
            g_attn[feat][(size_t)(r0 + 8) * 128 + col + 1] = o[mf][nd][3] * i1;
        }
    }
}

// ================= layernorm of (A + B) =================
__global__ void k_ln(int aId, int bId, int outId, const float* __restrict__ g,
                     const float* __restrict__ b) {
    __shared__ float rs[4], rq[4];
    int n = blockIdx.x, feat = blockIdx.y, t = threadIdx.x;
    const float* A = resolve(aId, feat);
    const float* B = resolve(bId, feat);
    float* O = resolve(outId, feat);
    float v = A[(size_t)n * 128 + t] + B[(size_t)n * 128 + t];
    float s = v, q = v * v;
    #pragma unroll
    for (int o = 16; o > 0; o >>= 1) {
        s += __shfl_xor_sync(0xffffffffu, s, o);
        q += __shfl_xor_sync(0xffffffffu, q, o);
    }
    int w = t >> 5;
    if ((t & 31) == 0) { rs[w] = s; rq[w] = q; }
    __syncthreads();
    s = rs[0] + rs[1] + rs[2] + rs[3];
    q = rq[0] + rq[1] + rq[2] + rq[3];
    float mean = s * (1.f / 128.f);
    float var = q * (1.f / 128.f) - mean * mean;
    O[(size_t)n * 128 + t] = (v - mean) * rsqrtf(var + 1e-5f) * g[t] + b[t];
}

// ================= final gating =================
__global__ void k_final(const float* __restrict__ x, const float* __restrict__ y,
                        float* __restrict__ out) {
    int i = blockIdx.x * 256 + threadIdx.x;
    float z = g_feat[0][i] + g_feat[1][i];
    float w = 1.f / (1.f + fast_exp(-z));
    out[i] = 2.f * (x[i] * w + y[i] * (1.f - w));
}

// ================= host orchestration =================
extern "C" void kernel_launch(void* const* d_in, const int* in_sizes, int n_in,
                              void* d_out, int out_size) {
    const float* x   = (const float*)d_in[0];
    const float* y   = (const float*)d_in[1];
    const float* pos = (const float*)d_in[2];
    const int*   nbr = (const int*)d_in[3];
    const float* Wx  = (const float*)d_in[5];
    const float* bx  = (const float*)d_in[6];
    const float* bxg = (const float*)d_in[7];
    const float* bxb = (const float*)d_in[8];
    const float* Wy  = (const float*)d_in[9];
    const float* by  = (const float*)d_in[10];
    const float* byg = (const float*)d_in[11];
    const float* byb = (const float*)d_in[12];
    const float* Wq  = (const float*)d_in[13];
    const float* bq  = (const float*)d_in[14];
    const float* Wk  = (const float*)d_in[15];
    const float* bk  = (const float*)d_in[16];
    const float* Wv  = (const float*)d_in[17];
    const float* bv  = (const float*)d_in[18];
    const float* Wo  = (const float*)d_in[19];
    const float* bo  = (const float*)d_in[20];
    const float* l1g = (const float*)d_in[21];
    const float* l1b = (const float*)d_in[22];
    const float* W1  = (const float*)d_in[23];
    const float* b1  = (const float*)d_in[24];
    const float* W2  = (const float*)d_in[25];
    const float* b2  = (const float*)d_in[26];
    const float* l2g = (const float*)d_in[27];
    const float* l2b = (const float*)d_in[28];
    float* out = (float*)d_out;

    cudaFuncSetAttribute(k_convmma, cudaFuncAttributeMaxDynamicSharedMemorySize, CONV_SMEM);

    k_posstats<<<1, 256>>>(pos);
    k_prepW<<<dim3(1024, 2), 128>>>(Wx, Wy);
    k_stageA<<<dim3(4096, 2), 128>>>(x, y, pos, nbr);
    k_convmma<<<dim3(64, 2, 2), 128, CONV_SMEM>>>(bx, by);
    k_bnstats<<<dim3(128, 2), 128>>>();
    k_bnrelu<<<dim3(4096, 2), 128>>>(bxg, bxb, byg, byb);

    // transformer block (both features fused via grid.z)
    k_addpe<<<dim3(4096, 2), 128>>>(pos);
    k_gemm<true><<<dim3(64, 3, 2), 128>>>(4, Wq, Wk, Wv, bq, bk, bv, 9, 128, 128, 16 | 8);
    k_attn_mma<<<dim3(32, 4, 2), 128>>>();
    k_gemm<true><<<dim3(64, 1, 2), 128>>>(8, Wo, Wo, Wo, bo, bo, bo, 9, 128, 128, 0);
    k_ln<<<dim3(4096, 2), 128>>>(2, 9, 10, l1g, l1b);
    k_gemm<true><<<dim3(64, 4, 2), 128>>>(10, W1, W1, W1, b1, b1, b1, 11, 128, 512, 1);
    k_gemm<true><<<dim3(64, 1, 2), 128>>>(11, W2, W2, W2, b2, b2, b2, 4, 512, 128, 0);
    k_ln<<<dim3(4096, 2), 128>>>(10, 4, 2, l2g, l2b);

    k_final<<<2048, 256>>>(x, y, out);
}

// round 15
// speedup vs baseline: 2.8725x; 1.0239x over previous
#include <cuda_runtime.h>
#include <cuda_bf16.h>
#include <math.h>
#include <stdint.h>

// ================= scratch (device globals; no allocation APIs) =================
#define NPTS 4096
__device__ __nv_bfloat16 g_Ah[2ull * NPTS * 8192];
__device__ __nv_bfloat16 g_Al[2ull * NPTS * 8192];
__device__ __nv_bfloat16 g_Wh[2ull * 128 * 8192];
__device__ __nv_bfloat16 g_Wl[2ull * 128 * 8192];
__device__ float g_convS[4][2][NPTS * 128];
__device__ float g_feat[2][NPTS * 128];
__device__ float g_h[2][NPTS * 128];
__device__ float g_attn[2][NPTS * 128];
__device__ float g_op[2][NPTS * 128];
__device__ float g_h1[2][NPTS * 128];
__device__ float g_ffh[2][NPTS * 512];
// bf16 hi/lo QKV for tensor attention.  q,k: [h][n][32]; v: [h][d][n]
__device__ __nv_bfloat16 g_qh[2ull * 524288], g_ql[2ull * 524288];
__device__ __nv_bfloat16 g_kh[2ull * 524288], g_kl[2ull * 524288];
__device__ __nv_bfloat16 g_vh[2ull * 524288], g_vl[2ull * 524288];
__device__ float g_stats[2][256];
__device__ float g_pstats[2];

__device__ __forceinline__ float* resolve(int id, int feat) {
    switch (id) {
        case 2:  return g_feat[feat];
        case 4:  return g_h[feat];
        case 8:  return g_attn[feat];
        case 9:  return g_op[feat];
        case 10: return g_h1[feat];
        default: return g_ffh[feat];
    }
}

// ================= baseline-PTX helpers (sm_103-safe) =================
static __device__ __forceinline__ uint32_t smem_u32(const void* p) {
    uint32_t a;
    asm("{ .reg .u64 t; cvta.to.shared.u64 t, %1; cvt.u32.u64 %0, t; }" : "=r"(a) : "l"(p));
    return a;
}
static __device__ __forceinline__ void cp_async16(uint32_t dst, const void* src) {
    asm volatile("cp.async.cg.shared.global [%0], [%1], 16;" :: "r"(dst), "l"(src) : "memory");
}
#define CP_COMMIT() asm volatile("cp.async.commit_group;" ::: "memory")
#define CP_WAIT(n)  asm volatile("cp.async.wait_group %0;" :: "n"(n) : "memory")

static __device__ __forceinline__ void ldm_x4(uint32_t* r, uint32_t addr) {
    asm volatile("ldmatrix.sync.aligned.m8n8.x4.shared.b16 {%0,%1,%2,%3}, [%4];"
                 : "=r"(r[0]), "=r"(r[1]), "=r"(r[2]), "=r"(r[3]) : "r"(addr));
}
static __device__ __forceinline__ void mma16816(float* c, const uint32_t* a, const uint32_t* b) {
    asm volatile("mma.sync.aligned.m16n8k16.row.col.f32.bf16.bf16.f32 "
                 "{%0,%1,%2,%3}, {%4,%5,%6,%7}, {%8,%9}, {%0,%1,%2,%3};"
                 : "+f"(c[0]), "+f"(c[1]), "+f"(c[2]), "+f"(c[3])
                 : "r"(a[0]), "r"(a[1]), "r"(a[2]), "r"(a[3]), "r"(b[0]), "r"(b[1]));
}

// fast exp on FMA pipe
__device__ __forceinline__ float fast_exp(float x) {
    float t = x * 1.4426950408889634f;
    t = fmaxf(t, -126.0f);
    float fi = floorf(t);
    float f  = t - fi;
    float r  = 1.5403530393381606e-4f;
    r = fmaf(r, f, 1.3333558146428443e-3f);
    r = fmaf(r, f, 9.6181291076284770e-3f);
    r = fmaf(r, f, 5.5504108664821580e-2f);
    r = fmaf(r, f, 2.4022650695910070e-1f);
    r = fmaf(r, f, 6.9314718055994530e-1f);
    r = fmaf(r, f, 1.0f);
    return r * __int_as_float(((int)fi + 127) << 23);
}

static __device__ __forceinline__ void pack_hilo(float a, float b, uint32_t& h, uint32_t& lo) {
    __nv_bfloat162 hh = __floats2bfloat162_rn(a, b);
    float2 hf = __bfloat1622float2(hh);
    __nv_bfloat162 ll = __floats2bfloat162_rn(a - hf.x, b - hf.y);
    h  = *reinterpret_cast<uint32_t*>(&hh);
    lo = *reinterpret_cast<uint32_t*>(&ll);
}

// ================= pos stats =================
__global__ void k_posstats(const float* __restrict__ pos) {
    __shared__ float ss[256], sq[256];
    int t = threadIdx.x;
    float s = 0.f, q = 0.f;
    for (int i = t; i < NPTS; i += 256) {
        float v = pos[i * 3];
        s += v; q = fmaf(v, v, q);
    }
    ss[t] = s; sq[t] = q;
    __syncthreads();
    for (int o = 128; o > 0; o >>= 1) {
        if (t < o) { ss[t] += ss[t + o]; sq[t] += sq[t + o]; }
        __syncthreads();
    }
    if (t == 0) {
        float m  = ss[0] / 4096.f;
        float sd = sqrtf(fmaxf((sq[0] - 4096.f * m * m) / 4095.f, 0.f));
        g_pstats[0] = m;
        g_pstats[1] = 1.f / (sd + 1e-8f);
    }
}

// ================= weight prep: transpose + bf16 hi/lo split -> W[o][k] =================
__global__ void k_prepW(const float* __restrict__ Wx, const float* __restrict__ Wy) {
    int feat = blockIdx.y;
    const float* W = feat ? Wy : Wx;
    __nv_bfloat16* Wh = g_Wh + (size_t)feat * 128 * 8192;
    __nv_bfloat16* Wl = g_Wl + (size_t)feat * 128 * 8192;
    int o = threadIdx.x;
    int k8 = blockIdx.x * 8;
    #pragma unroll
    for (int j = 0; j < 8; j++) {
        float v = W[(size_t)(k8 + j) * 128 + o];
        __nv_bfloat16 h = __float2bfloat16(v);
        __nv_bfloat16 l = __float2bfloat16(v - __bfloat162float(h));
        Wh[(size_t)o * 8192 + k8 + j] = h;
        Wl[(size_t)o * 8192 + k8 + j] = l;
    }
}

// ================= cconv stage A: scatter into A[n][64cells][128c], bf16 hi/lo out =================
__global__ __launch_bounds__(128) void k_stageA(const float* __restrict__ x,
                                                const float* __restrict__ y,
                                                const float* __restrict__ pos,
                                                const int* __restrict__ nbr) {
    __shared__ float A[64 * 128];
    __shared__ float wgt[80][8];
    __shared__ int   cel[80][8];
    __shared__ int   jl[80];
    __shared__ int   vld[80];
    int i = blockIdx.x;
    int feat = blockIdx.y;
    const float* src = feat ? y : x;
    int t = threadIdx.x;
    for (int u = t; u < 64 * 128; u += 128) A[u] = 0.f;
    if (t < 80) {
        int j = nbr[i * 80 + t];
        jl[t] = j;
        const float R = 0.1125f;
        float rx = (pos[3 * j + 0] - pos[3 * i + 0]) / R;
        float ry = (pos[3 * j + 1] - pos[3 * i + 1]) / R;
        float rz = (pos[3 * j + 2] - pos[3 * i + 2]) / R;
        float r2 = rx * rx + ry * ry + rz * rz;
        float win = 0.f;
        if (j != i) {
            float w1 = 1.f - r2;
            win = fminf(fmaxf(w1 * w1 * w1, 0.f), 1.f);
        }
        vld[t] = (win > 0.f) ? 1 : 0;
        float nrm  = sqrtf(fmaxf(r2, 1e-12f));
        float linf = fmaxf(fmaxf(fabsf(rx), fabsf(ry)), fabsf(rz));
        linf = fmaxf(linf, 1e-9f);
        float sc = nrm / linf;
        float gx = fminf(fmaxf(fmaf(rx * sc, 1.5f, 1.5f), 0.f), 3.f);
        float gy = fminf(fmaxf(fmaf(ry * sc, 1.5f, 1.5f), 0.f), 3.f);
        float gz = fminf(fmaxf(fmaf(rz * sc, 1.5f, 1.5f), 0.f), 3.f);
        float fx = fminf(floorf(gx), 2.f);
        float fy = fminf(floorf(gy), 2.f);
        float fz = fminf(floorf(gz), 2.f);
        float tx = gx - fx, ty = gy - fy, tz = gz - fz;
        int base = (int)fx * 16 + (int)fy * 4 + (int)fz;
        #pragma unroll
        for (int dx = 0; dx < 2; dx++)
            #pragma unroll
            for (int dy = 0; dy < 2; dy++)
                #pragma unroll
                for (int dz = 0; dz < 2; dz++) {
                    float cw = (dx ? tx : 1.f - tx) * (dy ? ty : 1.f - ty) * (dz ? tz : 1.f - tz);
                    int q = dx * 4 + dy * 2 + dz;
                    wgt[t][q] = win * cw;
                    cel[t][q] = base + dx * 16 + dy * 4 + dz;
                }
    }
    __syncthreads();
    int c = t;
    for (int nb = 0; nb < 80; nb++) {
        if (!vld[nb]) continue;
        float f = src[(size_t)jl[nb] * 128 + c];
        #pragma unroll
        for (int q = 0; q < 8; q++)
            A[cel[nb][q] * 128 + c] += wgt[nb][q] * f;
    }
    __syncthreads();
    __nv_bfloat16* dh = g_Ah + (size_t)feat * NPTS * 8192 + (size_t)i * 8192;
    __nv_bfloat16* dl = g_Al + (size_t)feat * NPTS * 8192 + (size_t)i * 8192;
    for (int u = t; u < 8192; u += 128) {
        float v = A[u];
        __nv_bfloat16 h = __float2bfloat16(v);
        dh[u] = h;
        dl[u] = __float2bfloat16(v - __bfloat162float(h));
    }
}

// ================= conv GEMM via mma.sync bf16 (3-term hi/lo split, split-K=4) =================
#define CONV_BUF 30720
#define CONV_SMEM (2 * CONV_BUF)
__global__ __launch_bounds__(128) void k_convmma(const float* __restrict__ biasX,
                                                 const float* __restrict__ biasY) {
    extern __shared__ __align__(16) char smem[];
    int t = threadIdx.x;
    int wid = t >> 5, l = t & 31;
    int mt = blockIdx.x, feat = blockIdx.y, kz = blockIdx.z;
    uint32_t sb = smem_u32(smem);

    const __nv_bfloat16* Ah = g_Ah + (size_t)feat * NPTS * 8192 + (size_t)mt * 64 * 8192;
    const __nv_bfloat16* Al = g_Al + (size_t)feat * NPTS * 8192 + (size_t)mt * 64 * 8192;
    const __nv_bfloat16* Wh = g_Wh + (size_t)feat * 128 * 8192;
    const __nv_bfloat16* Wl = g_Wl + (size_t)feat * 128 * 8192;

    auto load_tile = [&](int kt, int buf) {
        uint32_t base = sb + buf * CONV_BUF;
        #pragma unroll
        for (int i = 0; i < 12; i++) {
            int c = i * 128 + t;
            const __nv_bfloat16* src;
            uint32_t moff; int local;
            if (i < 2)      { src = Ah; moff = 0;     local = c; }
            else if (i < 4) { src = Al; moff = 5120;  local = c - 256; }
            else if (i < 8) { src = Wh; moff = 10240; local = c - 512; }
            else            { src = Wl; moff = 20480; local = c - 1024; }
            int row = local >> 2, kp = local & 3;
            cp_async16(base + moff + row * 80 + kp * 16,
                       src + (size_t)row * 8192 + kt * 32 + kp * 8);
        }
        CP_COMMIT();
    };

    int wm = wid & 1, wn = wid >> 1;
    float acc[2][8][4];
    #pragma unroll
    for (int a = 0; a < 2; a++)
        #pragma unroll
        for (int b = 0; b < 8; b++)
            #pragma unroll
            for (int cc = 0; cc < 4; cc++) acc[a][b][cc] = 0.f;

    const int NCHUNK = 64;              // 2048 K per split
    int kt0 = kz * NCHUNK;
    load_tile(kt0, 0);
    for (int kk = 0; kk < NCHUNK; kk++) {
        int kt = kt0 + kk;
        int buf = kk & 1;
        if (kk + 1 < NCHUNK) { load_tile(kt + 1, buf ^ 1); CP_WAIT(1); }
        else                 { CP_WAIT(0); }
        __syncthreads();
        uint32_t ab = sb + buf * CONV_BUF;
        #pragma unroll
        for (int k16 = 0; k16 < 2; k16++) {
            int kb2 = k16 * 32;
            uint32_t ah[2][4], al[2][4];
            #pragma unroll
            for (int mf = 0; mf < 2; mf++) {
                int row = wm * 32 + mf * 16 + (l & 15);
                uint32_t colb = kb2 + (l >> 4) * 16;
                ldm_x4(ah[mf], ab + 0    + row * 80 + colb);
                ldm_x4(al[mf], ab + 5120 + row * 80 + colb);
            }
            uint32_t wh[4][4], wl[4][4];
            #pragma unroll
            for (int ng = 0; ng < 4; ng++) {
                int row = wn * 64 + ng * 16 + (l & 7) + (l >> 4) * 8;
                uint32_t colb = kb2 + ((l >> 3) & 1) * 16;
                ldm_x4(wh[ng], ab + 10240 + row * 80 + colb);
                ldm_x4(wl[ng], ab + 20480 + row * 80 + colb);
            }
            #pragma unroll
            for (int mf = 0; mf < 2; mf++)
                #pragma unroll
                for (int ng = 0; ng < 4; ng++) {
                    mma16816(acc[mf][2 * ng],     ah[mf], &wh[ng][0]);
                    mma16816(acc[mf][2 * ng],     al[mf], &wh[ng][0]);
                    mma16816(acc[mf][2 * ng],     ah[mf], &wl[ng][0]);
                    mma16816(acc[mf][2 * ng + 1], ah[mf], &wh[ng][2]);
                    mma16816(acc[mf][2 * ng + 1], al[mf], &wh[ng][2]);
                    mma16816(acc[mf][2 * ng + 1], ah[mf], &wl[ng][2]);
                }
        }
        __syncthreads();
    }

    const float* bias = feat ? biasY : biasX;
    float* out = g_convS[kz][feat];
    #pragma unroll
    for (int mf = 0; mf < 2; mf++) {
        int r0 = mt * 64 + wm * 32 + mf * 16 + (l >> 2);
        #pragma unroll
        for (int nf = 0; nf < 8; nf++) {
            int col = wn * 64 + nf * 8 + (l & 3) * 2;
            float b0 = kz ? 0.f : bias[col];
            float b1 = kz ? 0.f : bias[col + 1];
            out[(size_t)r0 * 128 + col]           = acc[mf][nf][0] + b0;
            out[(size_t)r0 * 128 + col + 1]       = acc[mf][nf][1] + b1;
            out[(size_t)(r0 + 8) * 128 + col]     = acc[mf][nf][2] + b0;
            out[(size_t)(r0 + 8) * 128 + col + 1] = acc[mf][nf][3] + b1;
        }
    }
}

// ================= SIMT GEMM: Out = In @ W.T + b =================
// flags: 1=relu, 8=blockIdx.y selects weight, 16=bf16 hi/lo QKV store
template <bool WT>
__global__ __launch_bounds__(128) void k_gemm(int inId,
                                              const float* W0, const float* W1, const float* W2,
                                              const float* B0, const float* B1, const float* B2,
                                              int outId, int Kdim, int O, int flags) {
    __shared__ __align__(16) float InsT[16][64];
    __shared__ __align__(16) float Ws[16][128];
    int feat = blockIdx.z;
    int sel = (flags & 8) ? blockIdx.y : 0;
    const float* W = (sel == 0) ? W0 : (sel == 1) ? W1 : W2;
    const float* bias = (sel == 0) ? B0 : (sel == 1) ? B1 : B2;
    const float* In = resolve(inId, feat);
    float* Out = resolve(outId, feat);
    int t = threadIdx.x;
    int bm0 = blockIdx.x * 64;
    int bn0 = (flags & 8) ? 0 : blockIdx.y * 128;
    int tr = t >> 4, tc = t & 15;
    float acc[8][8];
    #pragma unroll
    for (int a = 0; a < 8; a++)
        #pragma unroll
        for (int b = 0; b < 8; b++) acc[a][b] = 0.f;

    for (int kb = 0; kb < Kdim; kb += 16) {
        __syncthreads();
        #pragma unroll
        for (int e = 0; e < 2; e++) {
            int f = t * 2 + e;
            int row = f >> 2;
            int k4 = (f & 3) * 4;
            float4 v = *(const float4*)&In[(size_t)(bm0 + row) * Kdim + kb + k4];
            InsT[k4 + 0][row] = v.x; InsT[k4 + 1][row] = v.y;
            InsT[k4 + 2][row] = v.z; InsT[k4 + 3][row] = v.w;
        }
        #pragma unroll
        for (int e = 0; e < 4; e++) {
            float4 v = *(const float4*)&W[(size_t)(bn0 + t) * Kdim + kb + e * 4];
            Ws[e * 4 + 0][t] = v.x; Ws[e * 4 + 1][t] = v.y;
            Ws[e * 4 + 2][t] = v.z; Ws[e * 4 + 3][t] = v.w;
        }
        __syncthreads();
        #pragma unroll
        for (int k = 0; k < 16; k++) {
            float a[8], w[8];
            *(float4*)&a[0] = *(const float4*)&InsT[k][tr * 8];
            *(float4*)&a[4] = *(const float4*)&InsT[k][tr * 8 + 4];
            *(float4*)&w[0] = *(const float4*)&Ws[k][tc * 8];
            *(float4*)&w[4] = *(const float4*)&Ws[k][tc * 8 + 4];
            #pragma unroll
            for (int ii = 0; ii < 8; ii++)
                #pragma unroll
                for (int jj = 0; jj < 8; jj++)
                    acc[ii][jj] = fmaf(a[ii], w[jj], acc[ii][jj]);
        }
    }
    #pragma unroll
    for (int ii = 0; ii < 8; ii++) {
        int n = bm0 + tr * 8 + ii;
        #pragma unroll
        for (int jj = 0; jj < 8; jj++) {
            int o = bn0 + tc * 8 + jj;
            float v = acc[ii][jj] + bias[o];
            if (flags & 16) {
                __nv_bfloat16* dh; __nv_bfloat16* dl; size_t idx;
                int head = o >> 5, d = o & 31;
                if (sel == 0) {
                    v *= 0.17677669529663687f;   // 1/sqrt(32)
                    dh = g_qh; dl = g_ql;
                    idx = (size_t)feat * 524288 + (size_t)head * 131072 + (size_t)n * 32 + d;
                } else if (sel == 1) {
                    dh = g_kh; dl = g_kl;
                    idx = (size_t)feat * 524288 + (size_t)head * 131072 + (size_t)n * 32 + d;
                } else {
                    dh = g_vh; dl = g_vl;
                    idx = (size_t)feat * 524288 + (size_t)head * 131072 + (size_t)d * 4096 + n;
                }
                __nv_bfloat16 h = __float2bfloat16(v);
                dh[idx] = h;
                dl[idx] = __float2bfloat16(v - __bfloat162float(h));
            } else {
                if (flags & 1) v = fmaxf(v, 0.f);
                Out[(size_t)n * O + o] = v;
            }
        }
    }
}

// ================= batch-norm stats (sums all 4 split-K buffers) =================
__global__ void k_bnstats() {
    __shared__ float ss[128], sq[128];
    int c = blockIdx.x, feat = blockIdx.y, t = threadIdx.x;
    float s = 0.f, q = 0.f;
    for (int r = t; r < NPTS; r += 128) {
        size_t i = (size_t)r * 128 + c;
        float v = (g_convS[0][feat][i] + g_convS[1][feat][i])
                + (g_convS[2][feat][i] + g_convS[3][feat][i]);
        s += v; q = fmaf(v, v, q);
    }
    ss[t] = s; sq[t] = q;
    __syncthreads();
    for (int o = 64; o > 0; o >>= 1) {
        if (t < o) { ss[t] += ss[t + o]; sq[t] += sq[t + o]; }
        __syncthreads();
    }
    if (t == 0) {
        float m = ss[0] / 4096.f;
        float var = sq[0] / 4096.f - m * m;
        g_stats[feat][c] = m;
        g_stats[feat][128 + c] = rsqrtf(var + 1e-5f);
    }
}

// ================= fused bn+relu+posenc: writes g_feat and g_h =================
__global__ void k_bnrelu_pe(const float* __restrict__ gx, const float* __restrict__ bx,
                            const float* __restrict__ gy, const float* __restrict__ by,
                            const float* __restrict__ pos) {
    int n = blockIdx.x, feat = blockIdx.y, c = threadIdx.x;
    const float* g = feat ? gy : gx;
    const float* b = feat ? by : bx;
    size_t i = (size_t)n * 128 + c;
    float v0 = (g_convS[0][feat][i] + g_convS[1][feat][i])
             + (g_convS[2][feat][i] + g_convS[3][feat][i]);
    float v = (v0 - g_stats[feat][c]) * g_stats[feat][128 + c] * g[c] + b[c];
    float f = fmaxf(v, 0.f);
    g_feat[feat][i] = f;
    float px = (pos[n * 3] - g_pstats[0]) * g_pstats[1];
    int hw = c >> 1;
    float ang = px * expf(-0.14391156831212798f * (float)hw);
    float pe = (c & 1) ? cosf(ang) : sinf(ang);
    g_h[feat][i] = f + pe;
}

// ================= flash attention via mma.sync bf16 (q-tile 64) =================
// CTA: 64 queries, one (head, feat). 4 warps x 16 queries. 32-key chunks, double buffered.
// smem: qh[64x80]@0, ql@5120, per-buf {kh@0,kl@2560,vh@5120,vl@7680} @ 10240+buf*10240.
__global__ __launch_bounds__(128) void k_attn_mma() {
    __shared__ __align__(16) char sm[30720];
    int t = threadIdx.x, wid = t >> 5, l = t & 31;
    int qt = blockIdx.x, head = blockIdx.y, feat = blockIdx.z;
    uint32_t sb = smem_u32(sm);

    const __nv_bfloat16* gqh = g_qh + (size_t)feat * 524288 + (size_t)head * 131072;
    const __nv_bfloat16* gql = g_ql + (size_t)feat * 524288 + (size_t)head * 131072;
    const __nv_bfloat16* gkh = g_kh + (size_t)feat * 524288 + (size_t)head * 131072;
    const __nv_bfloat16* gkl = g_kl + (size_t)feat * 524288 + (size_t)head * 131072;
    const __nv_bfloat16* gvh = g_vh + (size_t)feat * 524288 + (size_t)head * 131072;
    const __nv_bfloat16* gvl = g_vl + (size_t)feat * 524288 + (size_t)head * 131072;

    // load Q tile (64 x 32) hi/lo into smem, stride 80B
    #pragma unroll
    for (int i = 0; i < 2; i++) {
        int c = i * 128 + t;
        int row = c >> 2, cc = c & 3;
        size_t gidx = (size_t)(qt * 64 + row) * 32 + cc * 8;
        *(uint4*)(sm + row * 80 + cc * 16)        = *(const uint4*)(gqh + gidx);
        *(uint4*)(sm + 5120 + row * 80 + cc * 16) = *(const uint4*)(gql + gidx);
    }

    auto load_kv = [&](int ch, int buf) {
        uint32_t base = sb + 10240 + buf * 10240;
        #pragma unroll
        for (int i = 0; i < 4; i++) {
            int c = i * 128 + t;
            int which = c >> 7, local = c & 127;
            int row = local >> 2, cc = local & 3;
            const __nv_bfloat16* src;
            uint32_t off;
            size_t gidx;
            if (which == 0)      { src = gkh; off = 0;    gidx = (size_t)(ch * 32 + row) * 32 + cc * 8; }
            else if (which == 1) { src = gkl; off = 2560; gidx = (size_t)(ch * 32 + row) * 32 + cc * 8; }
            else if (which == 2) { src = gvh; off = 5120; gidx = (size_t)row * 4096 + ch * 32 + cc * 8; }
            else                 { src = gvl; off = 7680; gidx = (size_t)row * 4096 + ch * 32 + cc * 8; }
            cp_async16(base + off + row * 80 + cc * 16, src + gidx);
        }
        CP_COMMIT();
    };

    load_kv(0, 0);
    __syncthreads();

    // Q fragments (A layout): each warp owns 16 query rows
    uint32_t qah[2][4], qal[2][4];
    #pragma unroll
    for (int ks = 0; ks < 2; ks++) {
        int row = wid * 16 + (l & 15);
        uint32_t colb = ks * 32 + (l >> 4) * 16;
        ldm_x4(qah[ks], sb + row * 80 + colb);
        ldm_x4(qal[ks], sb + 5120 + row * 80 + colb);
    }

    float o[4][4];
    #pragma unroll
    for (int b = 0; b < 4; b++)
        #pragma unroll
        for (int c = 0; c < 4; c++) o[b][c] = 0.f;
    float mrow[2] = {-1e30f, -1e30f};
    float lrow[2] = {0.f, 0.f};

    const int NCH = 128;
    for (int ch = 0; ch < NCH; ch++) {
        int buf = ch & 1;
        if (ch + 1 < NCH) { load_kv(ch + 1, buf ^ 1); CP_WAIT(1); }
        else              { CP_WAIT(0); }
        __syncthreads();
        uint32_t kb = sb + 10240 + buf * 10240;

        uint32_t kbh[2][2][4], kbl[2][2][4];
        #pragma unroll
        for (int ng = 0; ng < 2; ng++)
            #pragma unroll
            for (int ks = 0; ks < 2; ks++) {
                int row = ng * 16 + (l & 7) + (l >> 4) * 8;
                uint32_t colb = ks * 32 + ((l >> 3) & 1) * 16;
                ldm_x4(kbh[ng][ks], kb + row * 80 + colb);
                ldm_x4(kbl[ng][ks], kb + 2560 + row * 80 + colb);
            }
        uint32_t vbh[2][2][4], vbl[2][2][4];
        #pragma unroll
        for (int g = 0; g < 2; g++)
            #pragma unroll
            for (int ks = 0; ks < 2; ks++) {
                int row = g * 16 + (l & 7) + (l >> 4) * 8;
                uint32_t colb = ks * 32 + ((l >> 3) & 1) * 16;
                ldm_x4(vbh[g][ks], kb + 5120 + row * 80 + colb);
                ldm_x4(vbl[g][ks], kb + 7680 + row * 80 + colb);
            }

        float s[4][4];
        #pragma unroll
        for (int n = 0; n < 4; n++)
            #pragma unroll
            for (int c = 0; c < 4; c++) s[n][c] = 0.f;
        #pragma unroll
        for (int ng = 0; ng < 2; ng++)
            #pragma unroll
            for (int ks = 0; ks < 2; ks++) {
                mma16816(s[2 * ng],     qah[ks], &kbh[ng][ks][0]);
                mma16816(s[2 * ng],     qal[ks], &kbh[ng][ks][0]);
                mma16816(s[2 * ng],     qah[ks], &kbl[ng][ks][0]);
                mma16816(s[2 * ng + 1], qah[ks], &kbh[ng][ks][2]);
                mma16816(s[2 * ng + 1], qal[ks], &kbh[ng][ks][2]);
                mma16816(s[2 * ng + 1], qah[ks], &kbl[ng][ks][2]);
            }
        // online softmax: rows r (c0,c1) and r+8 (c2,c3)
        float cm0 = fmaxf(fmaxf(s[0][0], s[0][1]), fmaxf(s[1][0], s[1][1]));
        cm0 = fmaxf(cm0, fmaxf(fmaxf(s[2][0], s[2][1]), fmaxf(s[3][0], s[3][1])));
        float cm1 = fmaxf(fmaxf(s[0][2], s[0][3]), fmaxf(s[1][2], s[1][3]));
        cm1 = fmaxf(cm1, fmaxf(fmaxf(s[2][2], s[2][3]), fmaxf(s[3][2], s[3][3])));
        cm0 = fmaxf(cm0, __shfl_xor_sync(0xffffffffu, cm0, 1));
        cm0 = fmaxf(cm0, __shfl_xor_sync(0xffffffffu, cm0, 2));
        cm1 = fmaxf(cm1, __shfl_xor_sync(0xffffffffu, cm1, 1));
        cm1 = fmaxf(cm1, __shfl_xor_sync(0xffffffffu, cm1, 2));
        float nm0 = fmaxf(mrow[0], cm0);
        float nm1 = fmaxf(mrow[1], cm1);
        float cr0 = fast_exp(mrow[0] - nm0);
        float cr1 = fast_exp(mrow[1] - nm1);
        mrow[0] = nm0; mrow[1] = nm1;
        lrow[0] *= cr0; lrow[1] *= cr1;
        #pragma unroll
        for (int nd = 0; nd < 4; nd++) {
            o[nd][0] *= cr0; o[nd][1] *= cr0;
            o[nd][2] *= cr1; o[nd][3] *= cr1;
        }
        uint32_t pah[2][4], pal[2][4];
        #pragma unroll
        for (int ks = 0; ks < 2; ks++) {
            int n0 = 2 * ks, n1 = 2 * ks + 1;
            float p00 = fast_exp(s[n0][0] - nm0), p01 = fast_exp(s[n0][1] - nm0);
            float p02 = fast_exp(s[n0][2] - nm1), p03 = fast_exp(s[n0][3] - nm1);
            float p10 = fast_exp(s[n1][0] - nm0), p11 = fast_exp(s[n1][1] - nm0);
            float p12 = fast_exp(s[n1][2] - nm1), p13 = fast_exp(s[n1][3] - nm1);
            lrow[0] += (p00 + p01) + (p10 + p11);
            lrow[1] += (p02 + p03) + (p12 + p13);
            pack_hilo(p00, p01, pah[ks][0], pal[ks][0]);
            pack_hilo(p02, p03, pah[ks][1], pal[ks][1]);
            pack_hilo(p10, p11, pah[ks][2], pal[ks][2]);
            pack_hilo(p12, p13, pah[ks][3], pal[ks][3]);
        }
        #pragma unroll
        for (int g = 0; g < 2; g++)
            #pragma unroll
            for (int ks = 0; ks < 2; ks++) {
                mma16816(o[2 * g],     pah[ks], &vbh[g][ks][0]);
                mma16816(o[2 * g],     pal[ks], &vbh[g][ks][0]);
                mma16816(o[2 * g],     pah[ks], &vbl[g][ks][0]);
                mma16816(o[2 * g + 1], pah[ks], &vbh[g][ks][2]);
                mma16816(o[2 * g + 1], pal[ks], &vbh[g][ks][2]);
                mma16816(o[2 * g + 1], pah[ks], &vbl[g][ks][2]);
            }
        __syncthreads();
    }

    // finalize: quad-reduce l, normalize, store
    float l0 = lrow[0], l1 = lrow[1];
    l0 += __shfl_xor_sync(0xffffffffu, l0, 1);
    l0 += __shfl_xor_sync(0xffffffffu, l0, 2);
    l1 += __shfl_xor_sync(0xffffffffu, l1, 1);
    l1 += __shfl_xor_sync(0xffffffffu, l1, 2);
    float i0 = 1.f / l0, i1 = 1.f / l1;
    int r0 = qt * 64 + wid * 16 + (l >> 2);
    #pragma unroll
    for (int nd = 0; nd < 4; nd++) {
        int col = head * 32 + nd * 8 + (l & 3) * 2;
        g_attn[feat][(size_t)r0 * 128 + col]           = o[nd][0] * i0;
        g_attn[feat][(size_t)r0 * 128 + col + 1]       = o[nd][1] * i0;
        g_attn[feat][(size_t)(r0 + 8) * 128 + col]     = o[nd][2] * i1;
        g_attn[feat][(size_t)(r0 + 8) * 128 + col + 1] = o[nd][3] * i1;
    }
}

// ================= layernorm of (A + B) =================
__global__ void k_ln(int aId, int bId, int outId, const float* __restrict__ g,
                     const float* __restrict__ b) {
    __shared__ float rs[4], rq[4];
    int n = blockIdx.x, feat = blockIdx.y, t = threadIdx.x;
    const float* A = resolve(aId, feat);
    const float* B = resolve(bId, feat);
    float* O = resolve(outId, feat);
    float v = A[(size_t)n * 128 + t] + B[(size_t)n * 128 + t];
    float s = v, q = v * v;
    #pragma unroll
    for (int o = 16; o > 0; o >>= 1) {
        s += __shfl_xor_sync(0xffffffffu, s, o);
        q += __shfl_xor_sync(0xffffffffu, q, o);
    }
    int w = t >> 5;
    if ((t & 31) == 0) { rs[w] = s; rq[w] = q; }
    __syncthreads();
    s = rs[0] + rs[1] + rs[2] + rs[3];
    q = rq[0] + rq[1] + rq[2] + rq[3];
    float mean = s * (1.f / 128.f);
    float var = q * (1.f / 128.f) - mean * mean;
    O[(size_t)n * 128 + t] = (v - mean) * rsqrtf(var + 1e-5f) * g[t] + b[t];
}

// ================= final gating =================
__global__ void k_final(const float* __restrict__ x, const float* __restrict__ y,
                        float* __restrict__ out) {
    int i = blockIdx.x * 256 + threadIdx.x;
    float z = g_feat[0][i] + g_feat[1][i];
    float w = 1.f / (1.f + fast_exp(-z));
    out[i] = 2.f * (x[i] * w + y[i] * (1.f - w));
}

// ================= host orchestration =================
extern "C" void kernel_launch(void* const* d_in, const int* in_sizes, int n_in,
                              void* d_out, int out_size) {
    const float* x   = (const float*)d_in[0];
    const float* y   = (const float*)d_in[1];
    const float* pos = (const float*)d_in[2];
    const int*   nbr = (const int*)d_in[3];
    const float* Wx  = (const float*)d_in[5];
    const float* bx  = (const float*)d_in[6];
    const float* bxg = (const float*)d_in[7];
    const float* bxb = (const float*)d_in[8];
    const float* Wy  = (const float*)d_in[9];
    const float* by  = (const float*)d_in[10];
    const float* byg = (const float*)d_in[11];
    const float* byb = (const float*)d_in[12];
    const float* Wq  = (const float*)d_in[13];
    const float* bq  = (const float*)d_in[14];
    const float* Wk  = (const float*)d_in[15];
    const float* bk  = (const float*)d_in[16];
    const float* Wv  = (const float*)d_in[17];
    const float* bv  = (const float*)d_in[18];
    const float* Wo  = (const float*)d_in[19];
    const float* bo  = (const float*)d_in[20];
    const float* l1g = (const float*)d_in[21];
    const float* l1b = (const float*)d_in[22];
    const float* W1  = (const float*)d_in[23];
    const float* b1  = (const float*)d_in[24];
    const float* W2  = (const float*)d_in[25];
    const float* b2  = (const float*)d_in[26];
    const float* l2g = (const float*)d_in[27];
    const float* l2b = (const float*)d_in[28];
    float* out = (float*)d_out;

    cudaFuncSetAttribute(k_convmma, cudaFuncAttributeMaxDynamicSharedMemorySize, CONV_SMEM);

    k_posstats<<<1, 256>>>(pos);
    k_prepW<<<dim3(1024, 2), 128>>>(Wx, Wy);
    k_stageA<<<dim3(4096, 2), 128>>>(x, y, pos, nbr);
    k_convmma<<<dim3(64, 2, 4), 128, CONV_SMEM>>>(bx, by);
    k_bnstats<<<dim3(128, 2), 128>>>();
    k_bnrelu_pe<<<dim3(4096, 2), 128>>>(bxg, bxb, byg, byb, pos);

    // transformer block (both features fused via grid.z)
    k_gemm<true><<<dim3(64, 3, 2), 128>>>(4, Wq, Wk, Wv, bq, bk, bv, 9, 128, 128, 16 | 8);
    k_attn_mma<<<dim3(64, 4, 2), 128>>>();
    k_gemm<true><<<dim3(64, 1, 2), 128>>>(8, Wo, Wo, Wo, bo, bo, bo, 9, 128, 128, 0);
    k_ln<<<dim3(4096, 2), 128>>>(2, 9, 10, l1g, l1b);
    k_gemm<true><<<dim3(64, 4, 2), 128>>>(10, W1, W1, W1, b1, b1, b1, 11, 128, 512, 1);
    k_gemm<true><<<dim3(64, 1, 2), 128>>>(11, W2, W2, W2, b2, b2, b2, 4, 512, 128, 0);
    k_ln<<<dim3(4096, 2), 128>>>(10, 4, 2, l2g, l2b);

    k_final<<<2048, 256>>>(x, y, out);
}

// round 16
// speedup vs baseline: 3.1712x; 1.1040x over previous
#include <cuda_runtime.h>
#include <cuda_bf16.h>
#include <math.h>
#include <stdint.h>

// ================= scratch (device globals; no allocation APIs) =================
#define NPTS 4096
__device__ __nv_bfloat16 g_Ah[2ull * NPTS * 8192];
__device__ __nv_bfloat16 g_Al[2ull * NPTS * 8192];
__device__ __nv_bfloat16 g_Wh[2ull * 128 * 8192];
__device__ __nv_bfloat16 g_Wl[2ull * 128 * 8192];
__device__ float g_convS[4][2][NPTS * 128];
__device__ float g_feat[2][NPTS * 128];
__device__ float g_h[2][NPTS * 128];      // FFN2 output (fp32)
__device__ float g_op[2][NPTS * 128];     // Wo output (fp32)
__device__ float g_h1[2][NPTS * 128];     // ln1 output (fp32)
// bf16 hi/lo operand arenas for tensor GEMMs
__device__ __nv_bfloat16 g_sWh[196608], g_sWl[196608];          // Wq|Wk|Wv|Wo|W1|W2
__device__ __nv_bfloat16 g_inh[2ull * 524288], g_inl[2ull * 524288];   // h = feat+pe
__device__ __nv_bfloat16 g_aoh[2ull * 524288], g_aol[2ull * 524288];   // attn out
__device__ __nv_bfloat16 g_l1h[2ull * 524288], g_l1l[2ull * 524288];   // ln1 out
__device__ __nv_bfloat16 g_fh[2ull * 2097152], g_fl[2ull * 2097152];   // FFN hidden
// bf16 hi/lo QKV.  q,k: [h][n][32]; v: [h][d][n]
__device__ __nv_bfloat16 g_qh[2ull * 524288], g_ql[2ull * 524288];
__device__ __nv_bfloat16 g_kh[2ull * 524288], g_kl[2ull * 524288];
__device__ __nv_bfloat16 g_vh[2ull * 524288], g_vl[2ull * 524288];
__device__ float g_stats[2][256];
__device__ float g_pstats[2];

__device__ __forceinline__ float* resolve(int id, int feat) {
    switch (id) {
        case 2:  return g_feat[feat];
        case 4:  return g_h[feat];
        case 9:  return g_op[feat];
        default: return g_h1[feat];
    }
}
__device__ __forceinline__ const __nv_bfloat16* rhi(int id) {
    switch (id) { case 0: return g_inh; case 1: return g_aoh; case 2: return g_l1h; default: return g_fh; }
}
__device__ __forceinline__ const __nv_bfloat16* rlo(int id) {
    switch (id) { case 0: return g_inl; case 1: return g_aol; case 2: return g_l1l; default: return g_fl; }
}

// ================= baseline-PTX helpers (sm_103-safe) =================
static __device__ __forceinline__ uint32_t smem_u32(const void* p) {
    uint32_t a;
    asm("{ .reg .u64 t; cvta.to.shared.u64 t, %1; cvt.u32.u64 %0, t; }" : "=r"(a) : "l"(p));
    return a;
}
static __device__ __forceinline__ void cp_async16(uint32_t dst, const void* src) {
    asm volatile("cp.async.cg.shared.global [%0], [%1], 16;" :: "r"(dst), "l"(src) : "memory");
}
#define CP_COMMIT() asm volatile("cp.async.commit_group;" ::: "memory")
#define CP_WAIT(n)  asm volatile("cp.async.wait_group %0;" :: "n"(n) : "memory")

static __device__ __forceinline__ void ldm_x4(uint32_t* r, uint32_t addr) {
    asm volatile("ldmatrix.sync.aligned.m8n8.x4.shared.b16 {%0,%1,%2,%3}, [%4];"
                 : "=r"(r[0]), "=r"(r[1]), "=r"(r[2]), "=r"(r[3]) : "r"(addr));
}
static __device__ __forceinline__ void mma16816(float* c, const uint32_t* a, const uint32_t* b) {
    asm volatile("mma.sync.aligned.m16n8k16.row.col.f32.bf16.bf16.f32 "
                 "{%0,%1,%2,%3}, {%4,%5,%6,%7}, {%8,%9}, {%0,%1,%2,%3};"
                 : "+f"(c[0]), "+f"(c[1]), "+f"(c[2]), "+f"(c[3])
                 : "r"(a[0]), "r"(a[1]), "r"(a[2]), "r"(a[3]), "r"(b[0]), "r"(b[1]));
}

// fast exp on FMA pipe
__device__ __forceinline__ float fast_exp(float x) {
    float t = x * 1.4426950408889634f;
    t = fmaxf(t, -126.0f);
    float fi = floorf(t);
    float f  = t - fi;
    float r  = 1.5403530393381606e-4f;
    r = fmaf(r, f, 1.3333558146428443e-3f);
    r = fmaf(r, f, 9.6181291076284770e-3f);
    r = fmaf(r, f, 5.5504108664821580e-2f);
    r = fmaf(r, f, 2.4022650695910070e-1f);
    r = fmaf(r, f, 6.9314718055994530e-1f);
    r = fmaf(r, f, 1.0f);
    return r * __int_as_float(((int)fi + 127) << 23);
}

static __device__ __forceinline__ void pack_hilo(float a, float b, uint32_t& h, uint32_t& lo) {
    __nv_bfloat162 hh = __floats2bfloat162_rn(a, b);
    float2 hf = __bfloat1622float2(hh);
    __nv_bfloat162 ll = __floats2bfloat162_rn(a - hf.x, b - hf.y);
    h  = *reinterpret_cast<uint32_t*>(&hh);
    lo = *reinterpret_cast<uint32_t*>(&ll);
}
static __device__ __forceinline__ void split_store(__nv_bfloat16* dh, __nv_bfloat16* dl,
                                                   size_t idx, float v) {
    __nv_bfloat16 h = __float2bfloat16(v);
    dh[idx] = h;
    dl[idx] = __float2bfloat16(v - __bfloat162float(h));
}

// ================= pos stats =================
__global__ void k_posstats(const float* __restrict__ pos) {
    __shared__ float ss[256], sq[256];
    int t = threadIdx.x;
    float s = 0.f, q = 0.f;
    for (int i = t; i < NPTS; i += 256) {
        float v = pos[i * 3];
        s += v; q = fmaf(v, v, q);
    }
    ss[t] = s; sq[t] = q;
    __syncthreads();
    for (int o = 128; o > 0; o >>= 1) {
        if (t < o) { ss[t] += ss[t + o]; sq[t] += sq[t + o]; }
        __syncthreads();
    }
    if (t == 0) {
        float m  = ss[0] / 4096.f;
        float sd = sqrtf(fmaxf((sq[0] - 4096.f * m * m) / 4095.f, 0.f));
        g_pstats[0] = m;
        g_pstats[1] = 1.f / (sd + 1e-8f);
    }
}

// ================= conv weight prep: transpose + hi/lo -> W[o][k] =================
__global__ void k_prepW(const float* __restrict__ Wx, const float* __restrict__ Wy) {
    int feat = blockIdx.y;
    const float* W = feat ? Wy : Wx;
    __nv_bfloat16* Wh = g_Wh + (size_t)feat * 128 * 8192;
    __nv_bfloat16* Wl = g_Wl + (size_t)feat * 128 * 8192;
    int o = threadIdx.x;
    int k8 = blockIdx.x * 8;
    #pragma unroll
    for (int j = 0; j < 8; j++) {
        float v = W[(size_t)(k8 + j) * 128 + o];
        split_store(Wh, Wl, (size_t)o * 8192 + k8 + j, v);
    }
}

// ================= small-weight prep: row-major [O][K] hi/lo into arena =================
__global__ void k_prepWS(const float* __restrict__ Wq, const float* __restrict__ Wk,
                         const float* __restrict__ Wv, const float* __restrict__ Wo,
                         const float* __restrict__ W1, const float* __restrict__ W2) {
    int i = blockIdx.x * 256 + threadIdx.x;      // 0..196607
    const float* src; int ofs;
    if      (i < 16384)  { src = Wq; ofs = 0; }
    else if (i < 32768)  { src = Wk; ofs = 16384; }
    else if (i < 49152)  { src = Wv; ofs = 32768; }
    else if (i < 65536)  { src = Wo; ofs = 49152; }
    else if (i < 131072) { src = W1; ofs = 65536; }
    else                 { src = W2; ofs = 131072; }
    split_store(g_sWh, g_sWl, i, src[i - ofs]);
}

// ================= cconv stage A =================
__global__ __launch_bounds__(128) void k_stageA(const float* __restrict__ x,
                                                const float* __restrict__ y,
                                                const float* __restrict__ pos,
                                                const int* __restrict__ nbr) {
    __shared__ float A[64 * 128];
    __shared__ float wgt[80][8];
    __shared__ int   cel[80][8];
    __shared__ int   jl[80];
    __shared__ int   vld[80];
    int i = blockIdx.x;
    int feat = blockIdx.y;
    const float* src = feat ? y : x;
    int t = threadIdx.x;
    for (int u = t; u < 64 * 128; u += 128) A[u] = 0.f;
    if (t < 80) {
        int j = nbr[i * 80 + t];
        jl[t] = j;
        const float R = 0.1125f;
        float rx = (pos[3 * j + 0] - pos[3 * i + 0]) / R;
        float ry = (pos[3 * j + 1] - pos[3 * i + 1]) / R;
        float rz = (pos[3 * j + 2] - pos[3 * i + 2]) / R;
        float r2 = rx * rx + ry * ry + rz * rz;
        float win = 0.f;
        if (j != i) {
            float w1 = 1.f - r2;
            win = fminf(fmaxf(w1 * w1 * w1, 0.f), 1.f);
        }
        vld[t] = (win > 0.f) ? 1 : 0;
        float nrm  = sqrtf(fmaxf(r2, 1e-12f));
        float linf = fmaxf(fmaxf(fabsf(rx), fabsf(ry)), fabsf(rz));
        linf = fmaxf(linf, 1e-9f);
        float sc = nrm / linf;
        float gx = fminf(fmaxf(fmaf(rx * sc, 1.5f, 1.5f), 0.f), 3.f);
        float gy = fminf(fmaxf(fmaf(ry * sc, 1.5f, 1.5f), 0.f), 3.f);
        float gz = fminf(fmaxf(fmaf(rz * sc, 1.5f, 1.5f), 0.f), 3.f);
        float fx = fminf(floorf(gx), 2.f);
        float fy = fminf(floorf(gy), 2.f);
        float fz = fminf(floorf(gz), 2.f);
        float tx = gx - fx, ty = gy - fy, tz = gz - fz;
        int base = (int)fx * 16 + (int)fy * 4 + (int)fz;
        #pragma unroll
        for (int dx = 0; dx < 2; dx++)
            #pragma unroll
            for (int dy = 0; dy < 2; dy++)
                #pragma unroll
                for (int dz = 0; dz < 2; dz++) {
                    float cw = (dx ? tx : 1.f - tx) * (dy ? ty : 1.f - ty) * (dz ? tz : 1.f - tz);
                    int q = dx * 4 + dy * 2 + dz;
                    wgt[t][q] = win * cw;
                    cel[t][q] = base + dx * 16 + dy * 4 + dz;
                }
    }
    __syncthreads();
    int c = t;
    for (int nb = 0; nb < 80; nb++) {
        if (!vld[nb]) continue;
        float f = src[(size_t)jl[nb] * 128 + c];
        #pragma unroll
        for (int q = 0; q < 8; q++)
            A[cel[nb][q] * 128 + c] += wgt[nb][q] * f;
    }
    __syncthreads();
    __nv_bfloat16* dh = g_Ah + (size_t)feat * NPTS * 8192 + (size_t)i * 8192;
    __nv_bfloat16* dl = g_Al + (size_t)feat * NPTS * 8192 + (size_t)i * 8192;
    for (int u = t; u < 8192; u += 128) split_store(dh, dl, u, A[u]);
}

// ================= conv GEMM (split-K=4), unchanged =================
#define CONV_BUF 30720
#define CONV_SMEM (2 * CONV_BUF)
__global__ __launch_bounds__(128) void k_convmma(const float* __restrict__ biasX,
                                                 const float* __restrict__ biasY) {
    extern __shared__ __align__(16) char smem[];
    int t = threadIdx.x;
    int wid = t >> 5, l = t & 31;
    int mt = blockIdx.x, feat = blockIdx.y, kz = blockIdx.z;
    uint32_t sb = smem_u32(smem);

    const __nv_bfloat16* Ah = g_Ah + (size_t)feat * NPTS * 8192 + (size_t)mt * 64 * 8192;
    const __nv_bfloat16* Al = g_Al + (size_t)feat * NPTS * 8192 + (size_t)mt * 64 * 8192;
    const __nv_bfloat16* Wh = g_Wh + (size_t)feat * 128 * 8192;
    const __nv_bfloat16* Wl = g_Wl + (size_t)feat * 128 * 8192;

    auto load_tile = [&](int kt, int buf) {
        uint32_t base = sb + buf * CONV_BUF;
        #pragma unroll
        for (int i = 0; i < 12; i++) {
            int c = i * 128 + t;
            const __nv_bfloat16* src;
            uint32_t moff; int local;
            if (i < 2)      { src = Ah; moff = 0;     local = c; }
            else if (i < 4) { src = Al; moff = 5120;  local = c - 256; }
            else if (i < 8) { src = Wh; moff = 10240; local = c - 512; }
            else            { src = Wl; moff = 20480; local = c - 1024; }
            int row = local >> 2, kp = local & 3;
            cp_async16(base + moff + row * 80 + kp * 16,
                       src + (size_t)row * 8192 + kt * 32 + kp * 8);
        }
        CP_COMMIT();
    };

    int wm = wid & 1, wn = wid >> 1;
    float acc[2][8][4];
    #pragma unroll
    for (int a = 0; a < 2; a++)
        #pragma unroll
        for (int b = 0; b < 8; b++)
            #pragma unroll
            for (int cc = 0; cc < 4; cc++) acc[a][b][cc] = 0.f;

    const int NCHUNK = 64;
    int kt0 = kz * NCHUNK;
    load_tile(kt0, 0);
    for (int kk = 0; kk < NCHUNK; kk++) {
        int kt = kt0 + kk;
        int buf = kk & 1;
        if (kk + 1 < NCHUNK) { load_tile(kt + 1, buf ^ 1); CP_WAIT(1); }
        else                 { CP_WAIT(0); }
        __syncthreads();
        uint32_t ab = sb + buf * CONV_BUF;
        #pragma unroll
        for (int k16 = 0; k16 < 2; k16++) {
            int kb2 = k16 * 32;
            uint32_t ah[2][4], al[2][4];
            #pragma unroll
            for (int mf = 0; mf < 2; mf++) {
                int row = wm * 32 + mf * 16 + (l & 15);
                uint32_t colb = kb2 + (l >> 4) * 16;
                ldm_x4(ah[mf], ab + 0    + row * 80 + colb);
                ldm_x4(al[mf], ab + 5120 + row * 80 + colb);
            }
            uint32_t wh[4][4], wl[4][4];
            #pragma unroll
            for (int ng = 0; ng < 4; ng++) {
                int row = wn * 64 + ng * 16 + (l & 7) + (l >> 4) * 8;
                uint32_t colb = kb2 + ((l >> 3) & 1) * 16;
                ldm_x4(wh[ng], ab + 10240 + row * 80 + colb);
                ldm_x4(wl[ng], ab + 20480 + row * 80 + colb);
            }
            #pragma unroll
            for (int mf = 0; mf < 2; mf++)
                #pragma unroll
                for (int ng = 0; ng < 4; ng++) {
                    mma16816(acc[mf][2 * ng],     ah[mf], &wh[ng][0]);
                    mma16816(acc[mf][2 * ng],     al[mf], &wh[ng][0]);
                    mma16816(acc[mf][2 * ng],     ah[mf], &wl[ng][0]);
                    mma16816(acc[mf][2 * ng + 1], ah[mf], &wh[ng][2]);
                    mma16816(acc[mf][2 * ng + 1], al[mf], &wh[ng][2]);
                    mma16816(acc[mf][2 * ng + 1], ah[mf], &wl[ng][2]);
                }
        }
        __syncthreads();
    }

    const float* bias = feat ? biasY : biasX;
    float* out = g_convS[kz][feat];
    #pragma unroll
    for (int mf = 0; mf < 2; mf++) {
        int r0 = mt * 64 + wm * 32 + mf * 16 + (l >> 2);
        #pragma unroll
        for (int nf = 0; nf < 8; nf++) {
            int col = wn * 64 + nf * 8 + (l & 3) * 2;
            float b0 = kz ? 0.f : bias[col];
            float b1 = kz ? 0.f : bias[col + 1];
            out[(size_t)r0 * 128 + col]           = acc[mf][nf][0] + b0;
            out[(size_t)r0 * 128 + col + 1]       = acc[mf][nf][1] + b1;
            out[(size_t)(r0 + 8) * 128 + col]     = acc[mf][nf][2] + b0;
            out[(size_t)(r0 + 8) * 128 + col + 1] = acc[mf][nf][3] + b1;
        }
    }
}

// ================= generic tensor GEMM for small mats =================
// Out[4096,O] = In[4096,Kdim] @ W^T, 3-term hi/lo. CTA 64m x 128n, K-chunk 32.
// mode: 0 = fp32+bias -> resolve(outId); 1 = relu+bias -> g_fh/g_fl hi/lo;
//       2 = QKV (blockIdx.y selects weight/bias; q scaled; v transposed).
__global__ __launch_bounds__(128) void k_tgemm(int inId, int Kdim, int wofs, int O,
                                               const float* B0, const float* B1, const float* B2,
                                               int outId, int mode) {
    extern __shared__ __align__(16) char smem[];
    int t = threadIdx.x;
    int wid = t >> 5, l = t & 31;
    int mt = blockIdx.x, feat = blockIdx.z;
    int sel = (mode == 2) ? blockIdx.y : 0;
    int bn0 = (mode == 2) ? 0 : blockIdx.y * 128;
    uint32_t sb = smem_u32(smem);
    size_t instride = (inId == 3) ? 2097152 : 524288;

    const __nv_bfloat16* Inh = rhi(inId) + (size_t)feat * instride + (size_t)mt * 64 * Kdim;
    const __nv_bfloat16* Inl = rlo(inId) + (size_t)feat * instride + (size_t)mt * 64 * Kdim;
    const __nv_bfloat16* Wh = g_sWh + wofs + sel * 16384 + (size_t)bn0 * Kdim;
    const __nv_bfloat16* Wl = g_sWl + wofs + sel * 16384 + (size_t)bn0 * Kdim;

    auto load_tile = [&](int kt, int buf) {
        uint32_t base = sb + buf * CONV_BUF;
        #pragma unroll
        for (int i = 0; i < 12; i++) {
            int c = i * 128 + t;
            const __nv_bfloat16* src;
            uint32_t moff; int local;
            if (i < 2)      { src = Inh; moff = 0;     local = c; }
            else if (i < 4) { src = Inl; moff = 5120;  local = c - 256; }
            else if (i < 8) { src = Wh;  moff = 10240; local = c - 512; }
            else            { src = Wl;  moff = 20480; local = c - 1024; }
            int row = local >> 2, kp = local & 3;
            cp_async16(base + moff + row * 80 + kp * 16,
                       src + (size_t)row * Kdim + kt * 32 + kp * 8);
        }
        CP_COMMIT();
    };

    int wm = wid & 1, wn = wid >> 1;
    float acc[2][8][4];
    #pragma unroll
    for (int a = 0; a < 2; a++)
        #pragma unroll
        for (int b = 0; b < 8; b++)
            #pragma unroll
            for (int cc = 0; cc < 4; cc++) acc[a][b][cc] = 0.f;

    int NCHUNK = Kdim >> 5;
    load_tile(0, 0);
    for (int kk = 0; kk < NCHUNK; kk++) {
        int buf = kk & 1;
        if (kk + 1 < NCHUNK) { load_tile(kk + 1, buf ^ 1); CP_WAIT(1); }
        else                 { CP_WAIT(0); }
        __syncthreads();
        uint32_t ab = sb + buf * CONV_BUF;
        #pragma unroll
        for (int k16 = 0; k16 < 2; k16++) {
            int kb2 = k16 * 32;
            uint32_t ah[2][4], al[2][4];
            #pragma unroll
            for (int mf = 0; mf < 2; mf++) {
                int row = wm * 32 + mf * 16 + (l & 15);
                uint32_t colb = kb2 + (l >> 4) * 16;
                ldm_x4(ah[mf], ab + 0    + row * 80 + colb);
                ldm_x4(al[mf], ab + 5120 + row * 80 + colb);
            }
            uint32_t wh[4][4], wl[4][4];
            #pragma unroll
            for (int ng = 0; ng < 4; ng++) {
                int row = wn * 64 + ng * 16 + (l & 7) + (l >> 4) * 8;
                uint32_t colb = kb2 + ((l >> 3) & 1) * 16;
                ldm_x4(wh[ng], ab + 10240 + row * 80 + colb);
                ldm_x4(wl[ng], ab + 20480 + row * 80 + colb);
            }
            #pragma unroll
            for (int mf = 0; mf < 2; mf++)
                #pragma unroll
                for (int ng = 0; ng < 4; ng++) {
                    mma16816(acc[mf][2 * ng],     ah[mf], &wh[ng][0]);
                    mma16816(acc[mf][2 * ng],     al[mf], &wh[ng][0]);
                    mma16816(acc[mf][2 * ng],     ah[mf], &wl[ng][0]);
                    mma16816(acc[mf][2 * ng + 1], ah[mf], &wh[ng][2]);
                    mma16816(acc[mf][2 * ng + 1], al[mf], &wh[ng][2]);
                    mma16816(acc[mf][2 * ng + 1], ah[mf], &wl[ng][2]);
                }
        }
        __syncthreads();
    }

    const float* bias = (sel == 0) ? B0 : (sel == 1) ? B1 : B2;
    float* Out = resolve(outId, feat);
    auto emit = [&](int n, int o, float v) {
        v += bias[o];
        if (mode == 0) {
            Out[(size_t)n * O + o] = v;
        } else if (mode == 1) {
            v = fmaxf(v, 0.f);
            size_t idx = (size_t)feat * 2097152 + (size_t)n * 512 + o;
            split_store(g_fh, g_fl, idx, v);
        } else {
            int head = o >> 5, d = o & 31;
            if (sel == 0) {
                v *= 0.17677669529663687f;
                split_store(g_qh, g_ql,
                            (size_t)feat * 524288 + (size_t)head * 131072 + (size_t)n * 32 + d, v);
            } else if (sel == 1) {
                split_store(g_kh, g_kl,
                            (size_t)feat * 524288 + (size_t)head * 131072 + (size_t)n * 32 + d, v);
            } else {
                split_store(g_vh, g_vl,
                            (size_t)feat * 524288 + (size_t)head * 131072 + (size_t)d * 4096 + n, v);
            }
        }
    };
    #pragma unroll
    for (int mf = 0; mf < 2; mf++) {
        int r0 = mt * 64 + wm * 32 + mf * 16 + (l >> 2);
        #pragma unroll
        for (int nf = 0; nf < 8; nf++) {
            int col = bn0 + wn * 64 + nf * 8 + (l & 3) * 2;
            emit(r0,     col,     acc[mf][nf][0]);
            emit(r0,     col + 1, acc[mf][nf][1]);
            emit(r0 + 8, col,     acc[mf][nf][2]);
            emit(r0 + 8, col + 1, acc[mf][nf][3]);
        }
    }
}

// ================= batch-norm stats =================
__global__ void k_bnstats() {
    __shared__ float ss[128], sq[128];
    int c = blockIdx.x, feat = blockIdx.y, t = threadIdx.x;
    float s = 0.f, q = 0.f;
    for (int r = t; r < NPTS; r += 128) {
        size_t i = (size_t)r * 128 + c;
        float v = (g_convS[0][feat][i] + g_convS[1][feat][i])
                + (g_convS[2][feat][i] + g_convS[3][feat][i]);
        s += v; q = fmaf(v, v, q);
    }
    ss[t] = s; sq[t] = q;
    __syncthreads();
    for (int o = 64; o > 0; o >>= 1) {
        if (t < o) { ss[t] += ss[t + o]; sq[t] += sq[t + o]; }
        __syncthreads();
    }
    if (t == 0) {
        float m = ss[0] / 4096.f;
        float var = sq[0] / 4096.f - m * m;
        g_stats[feat][c] = m;
        g_stats[feat][128 + c] = rsqrtf(var + 1e-5f);
    }
}

// ================= fused bn+relu+posenc: g_feat fp32, h hi/lo =================
__global__ void k_bnrelu_pe(const float* __restrict__ gx, const float* __restrict__ bx,
                            const float* __restrict__ gy, const float* __restrict__ by,
                            const float* __restrict__ pos) {
    int n = blockIdx.x, feat = blockIdx.y, c = threadIdx.x;
    const float* g = feat ? gy : gx;
    const float* b = feat ? by : bx;
    size_t i = (size_t)n * 128 + c;
    float v0 = (g_convS[0][feat][i] + g_convS[1][feat][i])
             + (g_convS[2][feat][i] + g_convS[3][feat][i]);
    float v = (v0 - g_stats[feat][c]) * g_stats[feat][128 + c] * g[c] + b[c];
    float f = fmaxf(v, 0.f);
    g_feat[feat][i] = f;
    float px = (pos[n * 3] - g_pstats[0]) * g_pstats[1];
    int hw = c >> 1;
    float ang = px * expf(-0.14391156831212798f * (float)hw);
    float pe = (c & 1) ? cosf(ang) : sinf(ang);
    split_store(g_inh, g_inl, (size_t)feat * 524288 + i, f + pe);
}

// ================= flash attention via mma.sync bf16 (q-tile 64) =================
__global__ __launch_bounds__(128) void k_attn_mma() {
    __shared__ __align__(16) char sm[30720];
    int t = threadIdx.x, wid = t >> 5, l = t & 31;
    int qt = blockIdx.x, head = blockIdx.y, feat = blockIdx.z;
    uint32_t sb = smem_u32(sm);

    const __nv_bfloat16* gqh = g_qh + (size_t)feat * 524288 + (size_t)head * 131072;
    const __nv_bfloat16* gql = g_ql + (size_t)feat * 524288 + (size_t)head * 131072;
    const __nv_bfloat16* gkh = g_kh + (size_t)feat * 524288 + (size_t)head * 131072;
    const __nv_bfloat16* gkl = g_kl + (size_t)feat * 524288 + (size_t)head * 131072;
    const __nv_bfloat16* gvh = g_vh + (size_t)feat * 524288 + (size_t)head * 131072;
    const __nv_bfloat16* gvl = g_vl + (size_t)feat * 524288 + (size_t)head * 131072;

    #pragma unroll
    for (int i = 0; i < 2; i++) {
        int c = i * 128 + t;
        int row = c >> 2, cc = c & 3;
        size_t gidx = (size_t)(qt * 64 + row) * 32 + cc * 8;
        *(uint4*)(sm + row * 80 + cc * 16)        = *(const uint4*)(gqh + gidx);
        *(uint4*)(sm + 5120 + row * 80 + cc * 16) = *(const uint4*)(gql + gidx);
    }

    auto load_kv = [&](int ch, int buf) {
        uint32_t base = sb + 10240 + buf * 10240;
        #pragma unroll
        for (int i = 0; i < 4; i++) {
            int c = i * 128 + t;
            int which = c >> 7, local = c & 127;
            int row = local >> 2, cc = local & 3;
            const __nv_bfloat16* src;
            uint32_t off;
            size_t gidx;
            if (which == 0)      { src = gkh; off = 0;    gidx = (size_t)(ch * 32 + row) * 32 + cc * 8; }
            else if (which == 1) { src = gkl; off = 2560; gidx = (size_t)(ch * 32 + row) * 32 + cc * 8; }
            else if (which == 2) { src = gvh; off = 5120; gidx = (size_t)row * 4096 + ch * 32 + cc * 8; }
            else                 { src = gvl; off = 7680; gidx = (size_t)row * 4096 + ch * 32 + cc * 8; }
            cp_async16(base + off + row * 80 + cc * 16, src + gidx);
        }
        CP_COMMIT();
    };

    load_kv(0, 0);
    __syncthreads();

    uint32_t qah[2][4], qal[2][4];
    #pragma unroll
    for (int ks = 0; ks < 2; ks++) {
        int row = wid * 16 + (l & 15);
        uint32_t colb = ks * 32 + (l >> 4) * 16;
        ldm_x4(qah[ks], sb + row * 80 + colb);
        ldm_x4(qal[ks], sb + 5120 + row * 80 + colb);
    }

    float o[4][4];
    #pragma unroll
    for (int b = 0; b < 4; b++)
        #pragma unroll
        for (int c = 0; c < 4; c++) o[b][c] = 0.f;
    float mrow[2] = {-1e30f, -1e30f};
    float lrow[2] = {0.f, 0.f};

    const int NCH = 128;
    for (int ch = 0; ch < NCH; ch++) {
        int buf = ch & 1;
        if (ch + 1 < NCH) { load_kv(ch + 1, buf ^ 1); CP_WAIT(1); }
        else              { CP_WAIT(0); }
        __syncthreads();
        uint32_t kb = sb + 10240 + buf * 10240;

        uint32_t kbh[2][2][4], kbl[2][2][4];
        #pragma unroll
        for (int ng = 0; ng < 2; ng++)
            #pragma unroll
            for (int ks = 0; ks < 2; ks++) {
                int row = ng * 16 + (l & 7) + (l >> 4) * 8;
                uint32_t colb = ks * 32 + ((l >> 3) & 1) * 16;
                ldm_x4(kbh[ng][ks], kb + row * 80 + colb);
                ldm_x4(kbl[ng][ks], kb + 2560 + row * 80 + colb);
            }
        uint32_t vbh[2][2][4], vbl[2][2][4];
        #pragma unroll
        for (int g = 0; g < 2; g++)
            #pragma unroll
            for (int ks = 0; ks < 2; ks++) {
                int row = g * 16 + (l & 7) + (l >> 4) * 8;
                uint32_t colb = ks * 32 + ((l >> 3) & 1) * 16;
                ldm_x4(vbh[g][ks], kb + 5120 + row * 80 + colb);
                ldm_x4(vbl[g][ks], kb + 7680 + row * 80 + colb);
            }

        float s[4][4];
        #pragma unroll
        for (int n = 0; n < 4; n++)
            #pragma unroll
            for (int c = 0; c < 4; c++) s[n][c] = 0.f;
        #pragma unroll
        for (int ng = 0; ng < 2; ng++)
            #pragma unroll
            for (int ks = 0; ks < 2; ks++) {
                mma16816(s[2 * ng],     qah[ks], &kbh[ng][ks][0]);
                mma16816(s[2 * ng],     qal[ks], &kbh[ng][ks][0]);
                mma16816(s[2 * ng],     qah[ks], &kbl[ng][ks][0]);
                mma16816(s[2 * ng + 1], qah[ks], &kbh[ng][ks][2]);
                mma16816(s[2 * ng + 1], qal[ks], &kbh[ng][ks][2]);
                mma16816(s[2 * ng + 1], qah[ks], &kbl[ng][ks][2]);
            }
        float cm0 = fmaxf(fmaxf(s[0][0], s[0][1]), fmaxf(s[1][0], s[1][1]));
        cm0 = fmaxf(cm0, fmaxf(fmaxf(s[2][0], s[2][1]), fmaxf(s[3][0], s[3][1])));
        float cm1 = fmaxf(fmaxf(s[0][2], s[0][3]), fmaxf(s[1][2], s[1][3]));
        cm1 = fmaxf(cm1, fmaxf(fmaxf(s[2][2], s[2][3]), fmaxf(s[3][2], s[3][3])));
        cm0 = fmaxf(cm0, __shfl_xor_sync(0xffffffffu, cm0, 1));
        cm0 = fmaxf(cm0, __shfl_xor_sync(0xffffffffu, cm0, 2));
        cm1 = fmaxf(cm1, __shfl_xor_sync(0xffffffffu, cm1, 1));
        cm1 = fmaxf(cm1, __shfl_xor_sync(0xffffffffu, cm1, 2));
        float nm0 = fmaxf(mrow[0], cm0);
        float nm1 = fmaxf(mrow[1], cm1);
        float cr0 = fast_exp(mrow[0] - nm0);
        float cr1 = fast_exp(mrow[1] - nm1);
        mrow[0] = nm0; mrow[1] = nm1;
        lrow[0] *= cr0; lrow[1] *= cr1;
        #pragma unroll
        for (int nd = 0; nd < 4; nd++) {
            o[nd][0] *= cr0; o[nd][1] *= cr0;
            o[nd][2] *= cr1; o[nd][3] *= cr1;
        }
        uint32_t pah[2][4], pal[2][4];
        #pragma unroll
        for (int ks = 0; ks < 2; ks++) {
            int n0 = 2 * ks, n1 = 2 * ks + 1;
            float p00 = fast_exp(s[n0][0] - nm0), p01 = fast_exp(s[n0][1] - nm0);
            float p02 = fast_exp(s[n0][2] - nm1), p03 = fast_exp(s[n0][3] - nm1);
            float p10 = fast_exp(s[n1][0] - nm0), p11 = fast_exp(s[n1][1] - nm0);
            float p12 = fast_exp(s[n1][2] - nm1), p13 = fast_exp(s[n1][3] - nm1);
            lrow[0] += (p00 + p01) + (p10 + p11);
            lrow[1] += (p02 + p03) + (p12 + p13);
            pack_hilo(p00, p01, pah[ks][0], pal[ks][0]);
            pack_hilo(p02, p03, pah[ks][1], pal[ks][1]);
            pack_hilo(p10, p11, pah[ks][2], pal[ks][2]);
            pack_hilo(p12, p13, pah[ks][3], pal[ks][3]);
        }
        #pragma unroll
        for (int g = 0; g < 2; g++)
            #pragma unroll
            for (int ks = 0; ks < 2; ks++) {
                mma16816(o[2 * g],     pah[ks], &vbh[g][ks][0]);
                mma16816(o[2 * g],     pal[ks], &vbh[g][ks][0]);
                mma16816(o[2 * g],     pah[ks], &vbl[g][ks][0]);
                mma16816(o[2 * g + 1], pah[ks], &vbh[g][ks][2]);
                mma16816(o[2 * g + 1], pal[ks], &vbh[g][ks][2]);
                mma16816(o[2 * g + 1], pah[ks], &vbl[g][ks][2]);
            }
        __syncthreads();
    }

    float l0 = lrow[0], l1 = lrow[1];
    l0 += __shfl_xor_sync(0xffffffffu, l0, 1);
    l0 += __shfl_xor_sync(0xffffffffu, l0, 2);
    l1 += __shfl_xor_sync(0xffffffffu, l1, 1);
    l1 += __shfl_xor_sync(0xffffffffu, l1, 2);
    float i0 = 1.f / l0, i1 = 1.f / l1;
    int r0 = qt * 64 + wid * 16 + (l >> 2);
    size_t fb = (size_t)feat * 524288;
    #pragma unroll
    for (int nd = 0; nd < 4; nd++) {
        int col = head * 32 + nd * 8 + (l & 3) * 2;
        split_store(g_aoh, g_aol, fb + (size_t)r0 * 128 + col,           o[nd][0] * i0);
        split_store(g_aoh, g_aol, fb + (size_t)r0 * 128 + col + 1,       o[nd][1] * i0);
        split_store(g_aoh, g_aol, fb + (size_t)(r0 + 8) * 128 + col,     o[nd][2] * i1);
        split_store(g_aoh, g_aol, fb + (size_t)(r0 + 8) * 128 + col + 1, o[nd][3] * i1);
    }
}

// ================= layernorm of (A + B), optional hi/lo emission =================
__global__ void k_ln(int aId, int bId, int outId, const float* __restrict__ g,
                     const float* __restrict__ b, int emitHL) {
    __shared__ float rs[4], rq[4];
    int n = blockIdx.x, feat = blockIdx.y, t = threadIdx.x;
    const float* A = resolve(aId, feat);
    const float* B = resolve(bId, feat);
    float* O = resolve(outId, feat);
    float v = A[(size_t)n * 128 + t] + B[(size_t)n * 128 + t];
    float s = v, q = v * v;
    #pragma unroll
    for (int o = 16; o > 0; o >>= 1) {
        s += __shfl_xor_sync(0xffffffffu, s, o);
        q += __shfl_xor_sync(0xffffffffu, q, o);
    }
    int w = t >> 5;
    if ((t & 31) == 0) { rs[w] = s; rq[w] = q; }
    __syncthreads();
    s = rs[0] + rs[1] + rs[2] + rs[3];
    q = rq[0] + rq[1] + rq[2] + rq[3];
    float mean = s * (1.f / 128.f);
    float var = q * (1.f / 128.f) - mean * mean;
    float outv = (v - mean) * rsqrtf(var + 1e-5f) * g[t] + b[t];
    O[(size_t)n * 128 + t] = outv;
    if (emitHL)
        split_store(g_l1h, g_l1l, (size_t)feat * 524288 + (size_t)n * 128 + t, outv);
}

// ================= final gating =================
__global__ void k_final(const float* __restrict__ x, const float* __restrict__ y,
                        float* __restrict__ out) {
    int i = blockIdx.x * 256 + threadIdx.x;
    float z = g_feat[0][i] + g_feat[1][i];
    float w = 1.f / (1.f + fast_exp(-z));
    out[i] = 2.f * (x[i] * w + y[i] * (1.f - w));
}

// ================= host orchestration =================
extern "C" void kernel_launch(void* const* d_in, const int* in_sizes, int n_in,
                              void* d_out, int out_size) {
    const float* x   = (const float*)d_in[0];
    const float* y   = (const float*)d_in[1];
    const float* pos = (const float*)d_in[2];
    const int*   nbr = (const int*)d_in[3];
    const float* Wx  = (const float*)d_in[5];
    const float* bx  = (const float*)d_in[6];
    const float* bxg = (const float*)d_in[7];
    const float* bxb = (const float*)d_in[8];
    const float* Wy  = (const float*)d_in[9];
    const float* by  = (const float*)d_in[10];
    const float* byg = (const float*)d_in[11];
    const float* byb = (const float*)d_in[12];
    const float* Wq  = (const float*)d_in[13];
    const float* bq  = (const float*)d_in[14];
    const float* Wk  = (const float*)d_in[15];
    const float* bk  = (const float*)d_in[16];
    const float* Wv  = (const float*)d_in[17];
    const float* bv  = (const float*)d_in[18];
    const float* Wo  = (const float*)d_in[19];
    const float* bo  = (const float*)d_in[20];
    const float* l1g = (const float*)d_in[21];
    const float* l1b = (const float*)d_in[22];
    const float* W1  = (const float*)d_in[23];
    const float* b1  = (const float*)d_in[24];
    const float* W2  = (const float*)d_in[25];
    const float* b2  = (const float*)d_in[26];
    const float* l2g = (const float*)d_in[27];
    const float* l2b = (const float*)d_in[28];
    float* out = (float*)d_out;

    cudaFuncSetAttribute(k_convmma, cudaFuncAttributeMaxDynamicSharedMemorySize, CONV_SMEM);
    cudaFuncSetAttribute(k_tgemm,  cudaFuncAttributeMaxDynamicSharedMemorySize, CONV_SMEM);

    k_posstats<<<1, 256>>>(pos);
    k_prepW<<<dim3(1024, 2), 128>>>(Wx, Wy);
    k_prepWS<<<768, 256>>>(Wq, Wk, Wv, Wo, W1, W2);
    k_stageA<<<dim3(4096, 2), 128>>>(x, y, pos, nbr);
    k_convmma<<<dim3(64, 2, 4), 128, CONV_SMEM>>>(bx, by);
    k_bnstats<<<dim3(128, 2), 128>>>();
    k_bnrelu_pe<<<dim3(4096, 2), 128>>>(bxg, bxb, byg, byb, pos);

    // transformer block (both features fused via grid.z), all GEMMs on tensor pipe
    k_tgemm<<<dim3(64, 3, 2), 128, CONV_SMEM>>>(0, 128, 0,      128, bq, bk, bv, 9, 2);  // QKV
    k_attn_mma<<<dim3(64, 4, 2), 128>>>();
    k_tgemm<<<dim3(64, 1, 2), 128, CONV_SMEM>>>(1, 128, 49152,  128, bo, bo, bo, 9, 0);  // Wo
    k_ln<<<dim3(4096, 2), 128>>>(2, 9, 10, l1g, l1b, 1);
    k_tgemm<<<dim3(64, 4, 2), 128, CONV_SMEM>>>(2, 128, 65536,  512, b1, b1, b1, 9, 1);  // FFN1
    k_tgemm<<<dim3(64, 1, 2), 128, CONV_SMEM>>>(3, 512, 131072, 128, b2, b2, b2, 4, 0);  // FFN2
    k_ln<<<dim3(4096, 2), 128>>>(10, 4, 2, l2g, l2b, 0);

    k_final<<<2048, 256>>>(x, y, out);
}